// round 1
// baseline (speedup 1.0000x reference)
#include <cuda_runtime.h>
#include <math.h>

#define SEQ 2048
#define EMB 1024
#define NH  16
#define HD  64

// Scratch (allocation-free rule: __device__ globals)
__device__ float g_q[SEQ * EMB];
__device__ float g_k[SEQ * HD];
__device__ float g_v[SEQ * HD];
__device__ float g_attn[SEQ * EMB];

// ---------------------------------------------------------------------------
// NT SGEMM: C[M,N] = A[M,K] @ B[N,K]^T + bias[N]
// A row-major [M,K], B row-major [N,K] (torch Linear weight layout).
// Register-blocked, single-buffered shared tiles.
// ---------------------------------------------------------------------------
template <int BM, int BN, int BK, int TM, int TN>
__global__ void __launch_bounds__((BM / TM) * (BN / TN))
sgemm_nt_bias(const float* __restrict__ A, const float* __restrict__ B,
              const float* __restrict__ bias, float* __restrict__ C,
              int M, int N, int K) {
    constexpr int THREADS = (BM / TM) * (BN / TN);
    __shared__ float As[BK][BM];
    __shared__ float Bs[BK][BN];

    const int tid = threadIdx.x;
    const int tx = tid % (BN / TN);
    const int ty = tid / (BN / TN);
    const int m0 = blockIdx.y * BM;
    const int n0 = blockIdx.x * BN;

    float acc[TM][TN] = {};

    for (int k0 = 0; k0 < K; k0 += BK) {
        // Load A tile (BM x BK), store transposed As[k][m]
        #pragma unroll
        for (int i = tid; i < BM * BK / 4; i += THREADS) {
            int row = i / (BK / 4);
            int c4  = i % (BK / 4);
            float4 val = *(const float4*)&A[(size_t)(m0 + row) * K + k0 + c4 * 4];
            As[c4 * 4 + 0][row] = val.x;
            As[c4 * 4 + 1][row] = val.y;
            As[c4 * 4 + 2][row] = val.z;
            As[c4 * 4 + 3][row] = val.w;
        }
        // Load B tile (BN x BK), store transposed Bs[k][n]
        #pragma unroll
        for (int i = tid; i < BN * BK / 4; i += THREADS) {
            int row = i / (BK / 4);
            int c4  = i % (BK / 4);
            float4 val = *(const float4*)&B[(size_t)(n0 + row) * K + k0 + c4 * 4];
            Bs[c4 * 4 + 0][row] = val.x;
            Bs[c4 * 4 + 1][row] = val.y;
            Bs[c4 * 4 + 2][row] = val.z;
            Bs[c4 * 4 + 3][row] = val.w;
        }
        __syncthreads();

        #pragma unroll
        for (int kk = 0; kk < BK; kk++) {
            float a[TM], b[TN];
            #pragma unroll
            for (int i = 0; i < TM; i++) a[i] = As[kk][ty * TM + i];
            #pragma unroll
            for (int j = 0; j < TN; j++) b[j] = Bs[kk][tx * TN + j];
            #pragma unroll
            for (int i = 0; i < TM; i++)
                #pragma unroll
                for (int j = 0; j < TN; j++)
                    acc[i][j] = fmaf(a[i], b[j], acc[i][j]);
        }
        __syncthreads();
    }

    #pragma unroll
    for (int i = 0; i < TM; i++) {
        int m = m0 + ty * TM + i;
        #pragma unroll
        for (int j = 0; j < TN; j += 4) {
            int n = n0 + tx * TN + j;
            float4 bv = *(const float4*)&bias[n];
            float4 o;
            o.x = acc[i][j + 0] + bv.x;
            o.y = acc[i][j + 1] + bv.y;
            o.z = acc[i][j + 2] + bv.z;
            o.w = acc[i][j + 3] + bv.w;
            *(float4*)&C[(size_t)m * N + n] = o;
        }
    }
}

// ---------------------------------------------------------------------------
// Causal multiquery attention, flash-style online softmax.
// One thread per query row; BQ=128 rows per block, grid.y = head.
// K/V shared by all heads (multiquery). Lazy rescale on max update.
// ---------------------------------------------------------------------------
__global__ void __launch_bounds__(128)
attn_kernel(const float* __restrict__ qb, const float* __restrict__ kb,
            const float* __restrict__ vb, float* __restrict__ ob) {
    constexpr int BQ = 128;
    constexpr int BKV = 64;

    const int h = blockIdx.y;
    const int qrow = blockIdx.x * BQ + threadIdx.x;

    __shared__ float4 Ks[BKV][HD / 4];
    __shared__ float4 Vs[BKV][HD / 4];

    float4 q[HD / 4];
    float4 o[HD / 4];
    const float4* qptr = (const float4*)&qb[(size_t)qrow * EMB + h * HD];
    #pragma unroll
    for (int i = 0; i < HD / 4; i++) {
        float4 t = qptr[i];
        // fold in 1/sqrt(D) = 1/8
        t.x *= 0.125f; t.y *= 0.125f; t.z *= 0.125f; t.w *= 0.125f;
        q[i] = t;
        o[i] = make_float4(0.f, 0.f, 0.f, 0.f);
    }

    float m = -1e30f, l = 0.f;
    const int kend = (blockIdx.x + 1) * BQ;  // causal: keys beyond q-block unused

    for (int k0 = 0; k0 < kend; k0 += BKV) {
        // Cooperative load of K/V tile
        for (int i = threadIdx.x; i < BKV * (HD / 4); i += BQ) {
            int r = i / (HD / 4);
            int c = i % (HD / 4);
            Ks[r][c] = *(const float4*)&kb[(size_t)(k0 + r) * HD + c * 4];
            Vs[r][c] = *(const float4*)&vb[(size_t)(k0 + r) * HD + c * 4];
        }
        __syncthreads();

        const int jmax = min(BKV, qrow - k0 + 1);
        for (int j = 0; j < jmax; j++) {
            // dot(q, k_j) with 4 independent accumulator lanes
            float sx = 0.f, sy = 0.f, sz = 0.f, sw = 0.f;
            #pragma unroll
            for (int i = 0; i < HD / 4; i++) {
                float4 kk = Ks[j][i];
                sx = fmaf(q[i].x, kk.x, sx);
                sy = fmaf(q[i].y, kk.y, sy);
                sz = fmaf(q[i].z, kk.z, sz);
                sw = fmaf(q[i].w, kk.w, sw);
            }
            float s = (sx + sy) + (sz + sw);

            float p;
            if (s > m) {
                // rare path: new running max -> rescale accumulators
                float corr = __expf(m - s);
                l *= corr;
                #pragma unroll
                for (int i = 0; i < HD / 4; i++) {
                    o[i].x *= corr; o[i].y *= corr;
                    o[i].z *= corr; o[i].w *= corr;
                }
                m = s;
                p = 1.f;
            } else {
                p = __expf(s - m);
            }
            l += p;
            #pragma unroll
            for (int i = 0; i < HD / 4; i++) {
                float4 vv = Vs[j][i];
                o[i].x = fmaf(p, vv.x, o[i].x);
                o[i].y = fmaf(p, vv.y, o[i].y);
                o[i].z = fmaf(p, vv.z, o[i].z);
                o[i].w = fmaf(p, vv.w, o[i].w);
            }
        }
        __syncthreads();
    }

    const float inv = 1.f / l;
    float4* optr = (float4*)&ob[(size_t)qrow * EMB + h * HD];
    #pragma unroll
    for (int i = 0; i < HD / 4; i++) {
        float4 t = o[i];
        t.x *= inv; t.y *= inv; t.z *= inv; t.w *= inv;
        optr[i] = t;
    }
}

// ---------------------------------------------------------------------------
// Launch: QKV proj -> attention -> output proj
// Inputs (metadata order): hidden_states, mask, Wq, bq, Wk, bk, Wv, bv, Wo, bo
// mask is ignored (causality is implemented directly).
// ---------------------------------------------------------------------------
extern "C" void kernel_launch(void* const* d_in, const int* in_sizes, int n_in,
                              void* d_out, int out_size) {
    const float* x  = (const float*)d_in[0];
    const float* Wq = (const float*)d_in[2];
    const float* bq = (const float*)d_in[3];
    const float* Wk = (const float*)d_in[4];
    const float* bk = (const float*)d_in[5];
    const float* Wv = (const float*)d_in[6];
    const float* bv = (const float*)d_in[7];
    const float* Wo = (const float*)d_in[8];
    const float* bo = (const float*)d_in[9];
    float* out = (float*)d_out;

    float *q, *k, *v, *attn;
    cudaGetSymbolAddress((void**)&q, g_q);
    cudaGetSymbolAddress((void**)&k, g_k);
    cudaGetSymbolAddress((void**)&v, g_v);
    cudaGetSymbolAddress((void**)&attn, g_attn);

    // Q projection: [2048,1024] = x @ Wq^T + bq
    sgemm_nt_bias<128, 128, 16, 8, 8>
        <<<dim3(EMB / 128, SEQ / 128), 256>>>(x, Wq, bq, q, SEQ, EMB, EMB);

    // K, V projections: [2048,64]
    sgemm_nt_bias<128, 64, 16, 8, 4>
        <<<dim3(1, SEQ / 128), 256>>>(x, Wk, bk, k, SEQ, HD, EMB);
    sgemm_nt_bias<128, 64, 16, 8, 4>
        <<<dim3(1, SEQ / 128), 256>>>(x, Wv, bv, v, SEQ, HD, EMB);

    // Attention (causal, multiquery)
    attn_kernel<<<dim3(SEQ / 128, NH), 128>>>(q, k, v, attn);

    // Output projection: out = attn @ Wo^T + bo
    sgemm_nt_bias<128, 128, 16, 8, 8>
        <<<dim3(EMB / 128, SEQ / 128), 256>>>(attn, Wo, bo, out, SEQ, EMB, EMB);
}

// round 2
// speedup vs baseline: 1.2479x; 1.2479x over previous
#include <cuda_runtime.h>
#include <math.h>

#define SEQ 2048
#define EMB 1024
#define NH  16
#define HD  64

// Scratch (allocation-free rule: __device__ globals)
__device__ float g_q[SEQ * EMB];
__device__ float g_k[SEQ * HD];
__device__ float g_v[SEQ * HD];
__device__ float g_attn[SEQ * EMB];

// ---------------------------------------------------------------------------
// NT SGEMM: C[M,N] = A[M,K] @ B[N,K]^T + bias[N]  (unchanged from R1)
// ---------------------------------------------------------------------------
template <int BM, int BN, int BK, int TM, int TN>
__global__ void __launch_bounds__((BM / TM) * (BN / TN))
sgemm_nt_bias(const float* __restrict__ A, const float* __restrict__ B,
              const float* __restrict__ bias, float* __restrict__ C,
              int M, int N, int K) {
    constexpr int THREADS = (BM / TM) * (BN / TN);
    __shared__ float As[BK][BM];
    __shared__ float Bs[BK][BN];

    const int tid = threadIdx.x;
    const int tx = tid % (BN / TN);
    const int ty = tid / (BN / TN);
    const int m0 = blockIdx.y * BM;
    const int n0 = blockIdx.x * BN;

    float acc[TM][TN] = {};

    for (int k0 = 0; k0 < K; k0 += BK) {
        #pragma unroll
        for (int i = tid; i < BM * BK / 4; i += THREADS) {
            int row = i / (BK / 4);
            int c4  = i % (BK / 4);
            float4 val = *(const float4*)&A[(size_t)(m0 + row) * K + k0 + c4 * 4];
            As[c4 * 4 + 0][row] = val.x;
            As[c4 * 4 + 1][row] = val.y;
            As[c4 * 4 + 2][row] = val.z;
            As[c4 * 4 + 3][row] = val.w;
        }
        #pragma unroll
        for (int i = tid; i < BN * BK / 4; i += THREADS) {
            int row = i / (BK / 4);
            int c4  = i % (BK / 4);
            float4 val = *(const float4*)&B[(size_t)(n0 + row) * K + k0 + c4 * 4];
            Bs[c4 * 4 + 0][row] = val.x;
            Bs[c4 * 4 + 1][row] = val.y;
            Bs[c4 * 4 + 2][row] = val.z;
            Bs[c4 * 4 + 3][row] = val.w;
        }
        __syncthreads();

        #pragma unroll
        for (int kk = 0; kk < BK; kk++) {
            float a[TM], b[TN];
            #pragma unroll
            for (int i = 0; i < TM; i++) a[i] = As[kk][ty * TM + i];
            #pragma unroll
            for (int j = 0; j < TN; j++) b[j] = Bs[kk][tx * TN + j];
            #pragma unroll
            for (int i = 0; i < TM; i++)
                #pragma unroll
                for (int j = 0; j < TN; j++)
                    acc[i][j] = fmaf(a[i], b[j], acc[i][j]);
        }
        __syncthreads();
    }

    #pragma unroll
    for (int i = 0; i < TM; i++) {
        int m = m0 + ty * TM + i;
        #pragma unroll
        for (int j = 0; j < TN; j += 4) {
            int n = n0 + tx * TN + j;
            float4 bv = *(const float4*)&bias[n];
            float4 o;
            o.x = acc[i][j + 0] + bv.x;
            o.y = acc[i][j + 1] + bv.y;
            o.z = acc[i][j + 2] + bv.z;
            o.w = acc[i][j + 3] + bv.w;
            *(float4*)&C[(size_t)m * N + n] = o;
        }
    }
}

// ---------------------------------------------------------------------------
// Causal multiquery attention, v2:
//   warp  = (head, 2 consecutive query rows), q held in registers (2x64)
//   block = 8 warps = 8 heads sharing K (transposed, +1 pad) / V tiles in smem
//   lanes parallelize over the 64-key tile; online softmax via shfl reductions
//   p exchanged via per-warp smem buffer, read back as float4 broadcasts
//   PV: lane owns output dims {2j, 2j+1} (float2), amortized over both rows
// ---------------------------------------------------------------------------
__global__ void __launch_bounds__(256, 1)
attn_kernel_v2(const float* __restrict__ qb, const float* __restrict__ kb,
               const float* __restrict__ vb, float* __restrict__ ob) {
    __shared__ float  Kt[HD][64 + 1];          // [dim][key], pad for store conflicts
    __shared__ float4 Vs[64][HD / 4];          // [key][dim/4]
    __shared__ float  pbuf[8][2][64];          // [warp][row][key]

    const int w = threadIdx.x >> 5;
    const int j = threadIdx.x & 31;

    // Heavy row-pairs first for wave balance
    const int rp = (int)gridDim.x - 1 - (int)blockIdx.x;
    const int r0 = rp * 2;
    const int r1 = r0 + 1;
    const int h  = blockIdx.y * 8 + w;

    // Load q for both rows into registers, fold in 1/sqrt(64)=0.125
    float q0[HD], q1[HD];
    {
        const float4* q0p = (const float4*)&qb[(size_t)r0 * EMB + h * HD];
        const float4* q1p = (const float4*)&qb[(size_t)r1 * EMB + h * HD];
        #pragma unroll
        for (int i = 0; i < HD / 4; i++) {
            float4 a = q0p[i];
            q0[4 * i + 0] = a.x * 0.125f; q0[4 * i + 1] = a.y * 0.125f;
            q0[4 * i + 2] = a.z * 0.125f; q0[4 * i + 3] = a.w * 0.125f;
            float4 b = q1p[i];
            q1[4 * i + 0] = b.x * 0.125f; q1[4 * i + 1] = b.y * 0.125f;
            q1[4 * i + 2] = b.z * 0.125f; q1[4 * i + 3] = b.w * 0.125f;
        }
    }

    float m0 = -1e30f, m1 = -1e30f, l0 = 0.f, l1 = 0.f;
    float2 o0 = make_float2(0.f, 0.f), o1 = make_float2(0.f, 0.f);

    const int nt = r1 / 64 + 1;

    for (int t = 0; t < nt; t++) {
        const int k0 = t * 64;

        __syncthreads();  // prior tile fully consumed (incl. pbuf reads)

        // Cooperative fill: K transposed, V direct. 256 threads, 4 iters.
        #pragma unroll
        for (int it = 0; it < 4; it++) {
            int idx = threadIdx.x + 256 * it;       // 0..1023
            int key = idx >> 4;
            int c   = idx & 15;
            float4 kk = *(const float4*)&kb[(size_t)(k0 + key) * HD + c * 4];
            Kt[c * 4 + 0][key] = kk.x;
            Kt[c * 4 + 1][key] = kk.y;
            Kt[c * 4 + 2][key] = kk.z;
            Kt[c * 4 + 3][key] = kk.w;
            Vs[key][c] = *(const float4*)&vb[(size_t)(k0 + key) * HD + c * 4];
        }
        __syncthreads();

        // Scores: lane j handles keys (k0+j) and (k0+j+32), both rows
        float s00 = 0.f, s01 = 0.f, s10 = 0.f, s11 = 0.f;
        #pragma unroll
        for (int i = 0; i < HD; i++) {
            float ka = Kt[i][j];
            float kc = Kt[i][j + 32];
            s00 = fmaf(q0[i], ka, s00);
            s01 = fmaf(q0[i], kc, s01);
            s10 = fmaf(q1[i], ka, s10);
            s11 = fmaf(q1[i], kc, s11);
        }

        // Causal mask
        const int kA = k0 + j;
        const int kB = k0 + j + 32;
        if (kA > r0) s00 = -1e30f;
        if (kB > r0) s01 = -1e30f;
        if (kA > r1) s10 = -1e30f;
        if (kB > r1) s11 = -1e30f;

        // Warp max per row
        float t0 = fmaxf(s00, s01);
        float t1 = fmaxf(s10, s11);
        #pragma unroll
        for (int d = 16; d > 0; d >>= 1) {
            t0 = fmaxf(t0, __shfl_xor_sync(0xFFFFFFFFu, t0, d));
            t1 = fmaxf(t1, __shfl_xor_sync(0xFFFFFFFFu, t1, d));
        }
        const float nm0 = fmaxf(m0, t0);
        const float nm1 = fmaxf(m1, t1);
        const float c0 = __expf(m0 - nm0);
        const float c1 = __expf(m1 - nm1);
        m0 = nm0; m1 = nm1;

        const float p00 = __expf(s00 - nm0);
        const float p01 = __expf(s01 - nm0);
        const float p10 = __expf(s10 - nm1);
        const float p11 = __expf(s11 - nm1);

        // Warp sum of p per row
        float ps0 = p00 + p01;
        float ps1 = p10 + p11;
        #pragma unroll
        for (int d = 16; d > 0; d >>= 1) {
            ps0 += __shfl_xor_sync(0xFFFFFFFFu, ps0, d);
            ps1 += __shfl_xor_sync(0xFFFFFFFFu, ps1, d);
        }
        l0 = l0 * c0 + ps0;
        l1 = l1 * c1 + ps1;
        o0.x *= c0; o0.y *= c0;
        o1.x *= c1; o1.y *= c1;

        // Publish p to this warp's buffer
        pbuf[w][0][j]      = p00;
        pbuf[w][0][j + 32] = p01;
        pbuf[w][1][j]      = p10;
        pbuf[w][1][j + 32] = p11;
        __syncwarp();

        // PV: lane owns dims {2j, 2j+1}; p read back as float4 broadcasts
        const float4* pa4 = (const float4*)pbuf[w][0];
        const float4* pb4 = (const float4*)pbuf[w][1];
        #pragma unroll
        for (int k4 = 0; k4 < 16; k4++) {
            float4 pa = pa4[k4];
            float4 pb = pb4[k4];
            #pragma unroll
            for (int e = 0; e < 4; e++) {
                const int key = 4 * k4 + e;
                float2 vv = ((const float2*)&Vs[key][0])[j];
                float pae = (e == 0) ? pa.x : (e == 1) ? pa.y : (e == 2) ? pa.z : pa.w;
                float pbe = (e == 0) ? pb.x : (e == 1) ? pb.y : (e == 2) ? pb.z : pb.w;
                o0.x = fmaf(pae, vv.x, o0.x);
                o0.y = fmaf(pae, vv.y, o0.y);
                o1.x = fmaf(pbe, vv.x, o1.x);
                o1.y = fmaf(pbe, vv.y, o1.y);
            }
        }
    }

    // Epilogue: normalize + store (float2 per lane, 256B contiguous per warp)
    const float inv0 = 1.f / l0;
    const float inv1 = 1.f / l1;
    float2* out0 = (float2*)&ob[(size_t)r0 * EMB + h * HD];
    float2* out1 = (float2*)&ob[(size_t)r1 * EMB + h * HD];
    out0[j] = make_float2(o0.x * inv0, o0.y * inv0);
    out1[j] = make_float2(o1.x * inv1, o1.y * inv1);
}

// ---------------------------------------------------------------------------
// Launch: QKV proj -> attention -> output proj
// Inputs: hidden_states, mask, Wq, bq, Wk, bk, Wv, bv, Wo, bo (mask ignored)
// ---------------------------------------------------------------------------
extern "C" void kernel_launch(void* const* d_in, const int* in_sizes, int n_in,
                              void* d_out, int out_size) {
    const float* x  = (const float*)d_in[0];
    const float* Wq = (const float*)d_in[2];
    const float* bq = (const float*)d_in[3];
    const float* Wk = (const float*)d_in[4];
    const float* bk = (const float*)d_in[5];
    const float* Wv = (const float*)d_in[6];
    const float* bv = (const float*)d_in[7];
    const float* Wo = (const float*)d_in[8];
    const float* bo = (const float*)d_in[9];
    float* out = (float*)d_out;

    float *q, *k, *v, *attn;
    cudaGetSymbolAddress((void**)&q, g_q);
    cudaGetSymbolAddress((void**)&k, g_k);
    cudaGetSymbolAddress((void**)&v, g_v);
    cudaGetSymbolAddress((void**)&attn, g_attn);

    // Q projection: [2048,1024] = x @ Wq^T + bq
    sgemm_nt_bias<128, 128, 16, 8, 8>
        <<<dim3(EMB / 128, SEQ / 128), 256>>>(x, Wq, bq, q, SEQ, EMB, EMB);

    // K, V projections: [2048,64]
    sgemm_nt_bias<128, 64, 16, 8, 4>
        <<<dim3(1, SEQ / 128), 256>>>(x, Wk, bk, k, SEQ, HD, EMB);
    sgemm_nt_bias<128, 64, 16, 8, 4>
        <<<dim3(1, SEQ / 128), 256>>>(x, Wv, bv, v, SEQ, HD, EMB);

    // Attention (causal, multiquery): 1024 row-pairs x 2 head-groups
    attn_kernel_v2<<<dim3(SEQ / 2, 2), 256>>>(q, k, v, attn);

    // Output projection: out = attn @ Wo^T + bo
    sgemm_nt_bias<128, 128, 16, 8, 8>
        <<<dim3(EMB / 128, SEQ / 128), 256>>>(attn, Wo, bo, out, SEQ, EMB, EMB);
}

// round 4
// speedup vs baseline: 1.8237x; 1.4614x over previous
#include <cuda_runtime.h>
#include <cuda_bf16.h>
#include <math.h>
#include <stdint.h>

#define SEQ 2048
#define EMB 1024
#define NH  16
#define HD  64

// Scratch (allocation-free rule: __device__ globals)
__device__ float g_q[SEQ * EMB];
__device__ float g_kv[SEQ * 128];     // [:,0:64]=K, [:,64:128]=V (fused)
__device__ float g_attn[SEQ * EMB];

// ===========================================================================
// Helpers (portable sm_80+ only: ldmatrix + mma.sync — NO tcgen05)
// ===========================================================================
__device__ __forceinline__ uint32_t smem_u32(const void* p) {
    uint32_t a;
    asm("{ .reg .u64 t; cvta.to.shared.u64 t, %1; cvt.u32.u64 %0, t; }"
        : "=r"(a) : "l"(p));
    return a;
}
__device__ __forceinline__ void ldm_x4(uint32_t& r0, uint32_t& r1,
                                       uint32_t& r2, uint32_t& r3, uint32_t a) {
    asm volatile("ldmatrix.sync.aligned.m8n8.x4.shared.b16 {%0,%1,%2,%3}, [%4];"
                 : "=r"(r0), "=r"(r1), "=r"(r2), "=r"(r3) : "r"(a));
}
__device__ __forceinline__ void mma_bf16(float* c, const uint32_t* a,
                                         const uint32_t* b) {
    asm volatile(
        "mma.sync.aligned.m16n8k16.row.col.f32.bf16.bf16.f32 "
        "{%0,%1,%2,%3}, {%4,%5,%6,%7}, {%8,%9}, {%0,%1,%2,%3};"
        : "+f"(c[0]), "+f"(c[1]), "+f"(c[2]), "+f"(c[3])
        : "r"(a[0]), "r"(a[1]), "r"(a[2]), "r"(a[3]), "r"(b[0]), "r"(b[1]));
}
__device__ __forceinline__ void sts64(uint32_t addr, uint32_t v0, uint32_t v1) {
    asm volatile("st.shared.v2.b32 [%0], {%1,%2};"
                 :: "r"(addr), "r"(v0), "r"(v1) : "memory");
}
// split (x,y) into packed bf16x2 hi and lo
__device__ __forceinline__ void split2(float x, float y, uint32_t& h, uint32_t& l) {
    __nv_bfloat16 hx = __float2bfloat16(x);
    __nv_bfloat16 hy = __float2bfloat16(y);
    __nv_bfloat16 lx = __float2bfloat16(x - __bfloat162float(hx));
    __nv_bfloat16 ly = __float2bfloat16(y - __bfloat162float(hy));
    h = ((uint32_t)__bfloat16_as_ushort(hy) << 16) | __bfloat16_as_ushort(hx);
    l = ((uint32_t)__bfloat16_as_ushort(ly) << 16) | __bfloat16_as_ushort(lx);
}

// ===========================================================================
// bf16 3x-split mma.sync GEMM: C[M,NC] = A[M,K] @ concat(B0,B1)[NC,K]^T + bias
//   D = Ah*Bh + Ah*Bl + Al*Bh  (fp32 accum; ~17-bit effective mantissa)
//   CTA tile BM x BN, BK=32, 8 warps, warp tile 32 x WN_.
//   smem rows: 32 bf16 (64B) padded to 80B -> conflict-free ldmatrix.
// ===========================================================================
template <int BM, int BN, int WN_>
__global__ void __launch_bounds__(256)
gemm_bf16x3(const float* __restrict__ A,
            const float* __restrict__ B0, const float* __restrict__ B1,
            const float* __restrict__ bias0, const float* __restrict__ bias1,
            int split, float* __restrict__ C, int NC, int K) {
    constexpr int WM_   = 32;
    constexpr int MFRAG = WM_ / 16;      // 2
    constexpr int NFRAG = WN_ / 8;
    constexpr int NWN   = BN / WN_;
    constexpr int FA    = BM / 32;       // float4 loads per thread for A
    constexpr int FB    = BN / 32;
    constexpr int ROW_B = 80;            // padded smem row bytes
    constexpr int SA    = BM * ROW_B;
    constexpr int SBB   = BN * ROW_B;
    constexpr int BUF   = 2 * SA + 2 * SBB;

    extern __shared__ char sm[];
    const uint32_t base = smem_u32(sm);

    const int tid  = threadIdx.x;
    const int w    = tid >> 5;
    const int lane = tid & 31;
    const int wm   = w / NWN;
    const int wn   = w % NWN;
    const int m0   = blockIdx.y * BM;
    const int n0   = blockIdx.x * BN;

    float acc[MFRAG][NFRAG][4] = {};
    float4 pa[FA], pb[FB];
    const int nch = K / 32;

    auto gload = [&](int ch) {
        const int k0 = ch * 32;
        #pragma unroll
        for (int t = 0; t < FA; t++) {
            int idx = tid + 256 * t, row = idx >> 3, c4 = idx & 7;
            pa[t] = *(const float4*)&A[(size_t)(m0 + row) * K + k0 + c4 * 4];
        }
        #pragma unroll
        for (int t = 0; t < FB; t++) {
            int idx = tid + 256 * t, row = idx >> 3, c4 = idx & 7;
            int gn = n0 + row;
            const float* bp = (gn < split) ? &B0[(size_t)gn * K]
                                           : &B1[(size_t)(gn - split) * K];
            pb[t] = *(const float4*)&bp[k0 + c4 * 4];
        }
    };
    auto ssts = [&](int buf) {
        const uint32_t Ah = base + buf * BUF;
        const uint32_t Al = Ah + SA;
        const uint32_t Bh = Ah + 2 * SA;
        const uint32_t Bl = Bh + SBB;
        #pragma unroll
        for (int t = 0; t < FA; t++) {
            int idx = tid + 256 * t, row = idx >> 3, c4 = idx & 7;
            uint32_t off = (uint32_t)(row * ROW_B + c4 * 8);
            uint32_t h0, l0, h1, l1;
            split2(pa[t].x, pa[t].y, h0, l0);
            split2(pa[t].z, pa[t].w, h1, l1);
            sts64(Ah + off, h0, h1);
            sts64(Al + off, l0, l1);
        }
        #pragma unroll
        for (int t = 0; t < FB; t++) {
            int idx = tid + 256 * t, row = idx >> 3, c4 = idx & 7;
            uint32_t off = (uint32_t)(row * ROW_B + c4 * 8);
            uint32_t h0, l0, h1, l1;
            split2(pb[t].x, pb[t].y, h0, l0);
            split2(pb[t].z, pb[t].w, h1, l1);
            sts64(Bh + off, h0, h1);
            sts64(Bl + off, l0, l1);
        }
    };
    auto compute = [&](int buf) {
        const uint32_t Ah = base + buf * BUF;
        const uint32_t Bh = Ah + 2 * SA;
        #pragma unroll
        for (int ks = 0; ks < 2; ks++) {
            uint32_t ah[MFRAG][4], al[MFRAG][4];
            uint32_t bh[NFRAG][2], bl[NFRAG][2];
            // A fragments: lanes 0-15 pick rows m0-15 @k0; 16-31 same rows @k8
            const uint32_t a_off =
                (uint32_t)((lane & 15) * ROW_B + (lane >> 4) * 16 + ks * 32);
            #pragma unroll
            for (int mf = 0; mf < MFRAG; mf++) {
                uint32_t ad = Ah + (uint32_t)((wm * WM_ + mf * 16) * ROW_B) + a_off;
                ldm_x4(ah[mf][0], ah[mf][1], ah[mf][2], ah[mf][3], ad);
                ldm_x4(al[mf][0], al[mf][1], al[mf][2], al[mf][3], ad + SA);
            }
            // B fragments: tiles (n0-7,k0),(n0-7,k8),(n8-15,k0),(n8-15,k8)
            const uint32_t b_off =
                (uint32_t)(((lane & 7) + ((lane >> 4) & 1) * 8) * ROW_B
                           + ((lane >> 3) & 1) * 16 + ks * 32);
            #pragma unroll
            for (int nf2 = 0; nf2 < NFRAG / 2; nf2++) {
                uint32_t bd = Bh + (uint32_t)((wn * WN_ + nf2 * 16) * ROW_B) + b_off;
                ldm_x4(bh[2 * nf2][0], bh[2 * nf2][1],
                       bh[2 * nf2 + 1][0], bh[2 * nf2 + 1][1], bd);
                ldm_x4(bl[2 * nf2][0], bl[2 * nf2][1],
                       bl[2 * nf2 + 1][0], bl[2 * nf2 + 1][1], bd + SBB);
            }
            #pragma unroll
            for (int mf = 0; mf < MFRAG; mf++)
                #pragma unroll
                for (int nf = 0; nf < NFRAG; nf++) {
                    mma_bf16(acc[mf][nf], ah[mf], bh[nf]);
                    mma_bf16(acc[mf][nf], ah[mf], bl[nf]);
                    mma_bf16(acc[mf][nf], al[mf], bh[nf]);
                }
        }
    };

    // Pipeline: double-buffered smem, regs hold chunk+1 while computing chunk
    gload(0);
    ssts(0);
    if (nch > 1) gload(1);
    __syncthreads();
    for (int ch = 0; ch < nch; ch++) {
        compute(ch & 1);
        if (ch + 1 < nch) {
            ssts((ch + 1) & 1);
            if (ch + 2 < nch) gload(ch + 2);
        }
        __syncthreads();
    }

    // Epilogue: add bias, store fp32
    const int g = lane >> 2, tig = lane & 3;
    #pragma unroll
    for (int mf = 0; mf < MFRAG; mf++) {
        const int r0 = m0 + wm * WM_ + mf * 16 + g;
        #pragma unroll
        for (int nf = 0; nf < NFRAG; nf++) {
            const int cN = n0 + wn * WN_ + nf * 8 + tig * 2;
            const float b0v = (cN < split) ? bias0[cN] : bias1[cN - split];
            const float b1v = (cN + 1 < split) ? bias0[cN + 1] : bias1[cN + 1 - split];
            float2 v0 = make_float2(acc[mf][nf][0] + b0v, acc[mf][nf][1] + b1v);
            float2 v1 = make_float2(acc[mf][nf][2] + b0v, acc[mf][nf][3] + b1v);
            *(float2*)&C[(size_t)r0 * NC + cN] = v0;
            *(float2*)&C[(size_t)(r0 + 8) * NC + cN] = v1;
        }
    }
}

// ===========================================================================
// Causal multiquery attention (v2; K/V from fused g_kv, stride 128)
// ===========================================================================
__global__ void __launch_bounds__(256, 1)
attn_kernel_v2(const float* __restrict__ qb, const float* __restrict__ kv,
               float* __restrict__ ob) {
    __shared__ float  Kt[HD][64 + 1];
    __shared__ float4 Vs[64][HD / 4];
    __shared__ float  pbuf[8][2][64];

    const int w = threadIdx.x >> 5;
    const int j = threadIdx.x & 31;

    const int rp = (int)gridDim.x - 1 - (int)blockIdx.x;
    const int r0 = rp * 2;
    const int r1 = r0 + 1;
    const int h  = blockIdx.y * 8 + w;

    float q0[HD], q1[HD];
    {
        const float4* q0p = (const float4*)&qb[(size_t)r0 * EMB + h * HD];
        const float4* q1p = (const float4*)&qb[(size_t)r1 * EMB + h * HD];
        #pragma unroll
        for (int i = 0; i < HD / 4; i++) {
            float4 a = q0p[i];
            q0[4 * i + 0] = a.x * 0.125f; q0[4 * i + 1] = a.y * 0.125f;
            q0[4 * i + 2] = a.z * 0.125f; q0[4 * i + 3] = a.w * 0.125f;
            float4 b = q1p[i];
            q1[4 * i + 0] = b.x * 0.125f; q1[4 * i + 1] = b.y * 0.125f;
            q1[4 * i + 2] = b.z * 0.125f; q1[4 * i + 3] = b.w * 0.125f;
        }
    }

    float m0 = -1e30f, m1 = -1e30f, l0 = 0.f, l1 = 0.f;
    float2 o0 = make_float2(0.f, 0.f), o1 = make_float2(0.f, 0.f);

    const int nt = r1 / 64 + 1;

    for (int t = 0; t < nt; t++) {
        const int k0 = t * 64;

        __syncthreads();

        #pragma unroll
        for (int it = 0; it < 4; it++) {
            int idx = threadIdx.x + 256 * it;
            int key = idx >> 4;
            int c   = idx & 15;
            float4 kk = *(const float4*)&kv[(size_t)(k0 + key) * 128 + c * 4];
            Kt[c * 4 + 0][key] = kk.x;
            Kt[c * 4 + 1][key] = kk.y;
            Kt[c * 4 + 2][key] = kk.z;
            Kt[c * 4 + 3][key] = kk.w;
            Vs[key][c] = *(const float4*)&kv[(size_t)(k0 + key) * 128 + 64 + c * 4];
        }
        __syncthreads();

        float s00 = 0.f, s01 = 0.f, s10 = 0.f, s11 = 0.f;
        #pragma unroll
        for (int i = 0; i < HD; i++) {
            float ka = Kt[i][j];
            float kc = Kt[i][j + 32];
            s00 = fmaf(q0[i], ka, s00);
            s01 = fmaf(q0[i], kc, s01);
            s10 = fmaf(q1[i], ka, s10);
            s11 = fmaf(q1[i], kc, s11);
        }

        const int kA = k0 + j;
        const int kB = k0 + j + 32;
        if (kA > r0) s00 = -1e30f;
        if (kB > r0) s01 = -1e30f;
        if (kA > r1) s10 = -1e30f;
        if (kB > r1) s11 = -1e30f;

        float t0 = fmaxf(s00, s01);
        float t1 = fmaxf(s10, s11);
        #pragma unroll
        for (int d = 16; d > 0; d >>= 1) {
            t0 = fmaxf(t0, __shfl_xor_sync(0xFFFFFFFFu, t0, d));
            t1 = fmaxf(t1, __shfl_xor_sync(0xFFFFFFFFu, t1, d));
        }
        const float nm0 = fmaxf(m0, t0);
        const float nm1 = fmaxf(m1, t1);
        const float c0 = __expf(m0 - nm0);
        const float c1 = __expf(m1 - nm1);
        m0 = nm0; m1 = nm1;

        const float p00 = __expf(s00 - nm0);
        const float p01 = __expf(s01 - nm0);
        const float p10 = __expf(s10 - nm1);
        const float p11 = __expf(s11 - nm1);

        float ps0 = p00 + p01;
        float ps1 = p10 + p11;
        #pragma unroll
        for (int d = 16; d > 0; d >>= 1) {
            ps0 += __shfl_xor_sync(0xFFFFFFFFu, ps0, d);
            ps1 += __shfl_xor_sync(0xFFFFFFFFu, ps1, d);
        }
        l0 = l0 * c0 + ps0;
        l1 = l1 * c1 + ps1;
        o0.x *= c0; o0.y *= c0;
        o1.x *= c1; o1.y *= c1;

        pbuf[w][0][j]      = p00;
        pbuf[w][0][j + 32] = p01;
        pbuf[w][1][j]      = p10;
        pbuf[w][1][j + 32] = p11;
        __syncwarp();

        const float4* pa4 = (const float4*)pbuf[w][0];
        const float4* pb4 = (const float4*)pbuf[w][1];
        #pragma unroll
        for (int k4 = 0; k4 < 16; k4++) {
            float4 pa = pa4[k4];
            float4 pb = pb4[k4];
            #pragma unroll
            for (int e = 0; e < 4; e++) {
                const int key = 4 * k4 + e;
                float2 vv = ((const float2*)&Vs[key][0])[j];
                float pae = (e == 0) ? pa.x : (e == 1) ? pa.y : (e == 2) ? pa.z : pa.w;
                float pbe = (e == 0) ? pb.x : (e == 1) ? pb.y : (e == 2) ? pb.z : pb.w;
                o0.x = fmaf(pae, vv.x, o0.x);
                o0.y = fmaf(pae, vv.y, o0.y);
                o1.x = fmaf(pbe, vv.x, o1.x);
                o1.y = fmaf(pbe, vv.y, o1.y);
            }
        }
    }

    const float inv0 = 1.f / l0;
    const float inv1 = 1.f / l1;
    float2* out0 = (float2*)&ob[(size_t)r0 * EMB + h * HD];
    float2* out1 = (float2*)&ob[(size_t)r1 * EMB + h * HD];
    out0[j] = make_float2(o0.x * inv0, o0.y * inv0);
    out1[j] = make_float2(o1.x * inv1, o1.y * inv1);
}

// ===========================================================================
// Launch
// Inputs: hidden_states, mask, Wq, bq, Wk, bk, Wv, bv, Wo, bo (mask ignored)
// ===========================================================================
extern "C" void kernel_launch(void* const* d_in, const int* in_sizes, int n_in,
                              void* d_out, int out_size) {
    const float* x  = (const float*)d_in[0];
    const float* Wq = (const float*)d_in[2];
    const float* bq = (const float*)d_in[3];
    const float* Wk = (const float*)d_in[4];
    const float* bk = (const float*)d_in[5];
    const float* Wv = (const float*)d_in[6];
    const float* bv = (const float*)d_in[7];
    const float* Wo = (const float*)d_in[8];
    const float* bo = (const float*)d_in[9];
    float* out = (float*)d_out;

    float *q, *kv, *attn;
    cudaGetSymbolAddress((void**)&q, g_q);
    cudaGetSymbolAddress((void**)&kv, g_kv);
    cudaGetSymbolAddress((void**)&attn, g_attn);

    // smem: 2 buffers * (2*BM + 2*BN) * 80 bytes
    const int SMEM_BIG = 2 * (2 * 128 + 2 * 128) * 80;   // 81920
    const int SMEM_KV  = 2 * (2 * 32 + 2 * 128) * 80;    // 51200
    cudaFuncSetAttribute((const void*)gemm_bf16x3<128, 128, 64>,
                         cudaFuncAttributeMaxDynamicSharedMemorySize, SMEM_BIG);
    cudaFuncSetAttribute((const void*)gemm_bf16x3<32, 128, 16>,
                         cudaFuncAttributeMaxDynamicSharedMemorySize, SMEM_KV);

    const int BIG = 1 << 30;

    // Q projection: [2048,1024] = x @ Wq^T + bq
    gemm_bf16x3<128, 128, 64><<<dim3(EMB / 128, SEQ / 128), 256, SMEM_BIG>>>(
        x, Wq, Wq, bq, bq, BIG, q, EMB, EMB);

    // Fused K|V projection: [2048,128] = x @ concat(Wk,Wv)^T + concat(bk,bv)
    gemm_bf16x3<32, 128, 16><<<dim3(1, SEQ / 32), 256, SMEM_KV>>>(
        x, Wk, Wv, bk, bv, HD, kv, 128, EMB);

    // Attention (causal, multiquery)
    attn_kernel_v2<<<dim3(SEQ / 2, 2), 256>>>(q, kv, attn);

    // Output projection: out = attn @ Wo^T + bo
    gemm_bf16x3<128, 128, 64><<<dim3(EMB / 128, SEQ / 128), 256, SMEM_BIG>>>(
        attn, Wo, Wo, bo, bo, BIG, out, EMB, EMB);
}

// round 5
// speedup vs baseline: 3.8373x; 2.1042x over previous
#include <cuda_runtime.h>
#include <cuda_bf16.h>
#include <math.h>
#include <stdint.h>

#define SEQ 2048
#define EMB 1024
#define NH  16
#define HD  64

// Scratch (allocation-free rule: __device__ globals)
__device__ float g_q[SEQ * EMB];
__device__ float g_kv[SEQ * 128];     // [:,0:64]=K, [:,64:128]=V (fused)
__device__ float g_attn[SEQ * EMB];

// ===========================================================================
// Helpers (portable sm_80+ only: ldmatrix + mma.sync — NO tcgen05)
// ===========================================================================
__device__ __forceinline__ uint32_t smem_u32(const void* p) {
    uint32_t a;
    asm("{ .reg .u64 t; cvta.to.shared.u64 t, %1; cvt.u32.u64 %0, t; }"
        : "=r"(a) : "l"(p));
    return a;
}
__device__ __forceinline__ void ldm_x4(uint32_t& r0, uint32_t& r1,
                                       uint32_t& r2, uint32_t& r3, uint32_t a) {
    asm volatile("ldmatrix.sync.aligned.m8n8.x4.shared.b16 {%0,%1,%2,%3}, [%4];"
                 : "=r"(r0), "=r"(r1), "=r"(r2), "=r"(r3) : "r"(a));
}
__device__ __forceinline__ void ldm_x4_t(uint32_t& r0, uint32_t& r1,
                                         uint32_t& r2, uint32_t& r3, uint32_t a) {
    asm volatile("ldmatrix.sync.aligned.m8n8.x4.trans.shared.b16 {%0,%1,%2,%3}, [%4];"
                 : "=r"(r0), "=r"(r1), "=r"(r2), "=r"(r3) : "r"(a));
}
__device__ __forceinline__ void mma_bf16(float* c, const uint32_t* a,
                                         const uint32_t* b) {
    asm volatile(
        "mma.sync.aligned.m16n8k16.row.col.f32.bf16.bf16.f32 "
        "{%0,%1,%2,%3}, {%4,%5,%6,%7}, {%8,%9}, {%0,%1,%2,%3};"
        : "+f"(c[0]), "+f"(c[1]), "+f"(c[2]), "+f"(c[3])
        : "r"(a[0]), "r"(a[1]), "r"(a[2]), "r"(a[3]), "r"(b[0]), "r"(b[1]));
}
__device__ __forceinline__ void sts64(uint32_t addr, uint32_t v0, uint32_t v1) {
    asm volatile("st.shared.v2.b32 [%0], {%1,%2};"
                 :: "r"(addr), "r"(v0), "r"(v1) : "memory");
}
// split (x,y) into packed bf16x2 hi and lo
__device__ __forceinline__ void split2(float x, float y, uint32_t& h, uint32_t& l) {
    __nv_bfloat16 hx = __float2bfloat16(x);
    __nv_bfloat16 hy = __float2bfloat16(y);
    __nv_bfloat16 lx = __float2bfloat16(x - __bfloat162float(hx));
    __nv_bfloat16 ly = __float2bfloat16(y - __bfloat162float(hy));
    h = ((uint32_t)__bfloat16_as_ushort(hy) << 16) | __bfloat16_as_ushort(hx);
    l = ((uint32_t)__bfloat16_as_ushort(ly) << 16) | __bfloat16_as_ushort(lx);
}

// ===========================================================================
// bf16 3x-split mma.sync GEMM (unchanged from R4)
// ===========================================================================
template <int BM, int BN, int WN_>
__global__ void __launch_bounds__(256)
gemm_bf16x3(const float* __restrict__ A,
            const float* __restrict__ B0, const float* __restrict__ B1,
            const float* __restrict__ bias0, const float* __restrict__ bias1,
            int split, float* __restrict__ C, int NC, int K) {
    constexpr int WM_   = 32;
    constexpr int MFRAG = WM_ / 16;
    constexpr int NFRAG = WN_ / 8;
    constexpr int NWN   = BN / WN_;
    constexpr int FA    = BM / 32;
    constexpr int FB    = BN / 32;
    constexpr int ROW_B = 80;
    constexpr int SA    = BM * ROW_B;
    constexpr int SBB   = BN * ROW_B;
    constexpr int BUF   = 2 * SA + 2 * SBB;

    extern __shared__ char sm[];
    const uint32_t base = smem_u32(sm);

    const int tid  = threadIdx.x;
    const int w    = tid >> 5;
    const int lane = tid & 31;
    const int wm   = w / NWN;
    const int wn   = w % NWN;
    const int m0   = blockIdx.y * BM;
    const int n0   = blockIdx.x * BN;

    float acc[MFRAG][NFRAG][4] = {};
    float4 pa[FA], pb[FB];
    const int nch = K / 32;

    auto gload = [&](int ch) {
        const int k0 = ch * 32;
        #pragma unroll
        for (int t = 0; t < FA; t++) {
            int idx = tid + 256 * t, row = idx >> 3, c4 = idx & 7;
            pa[t] = *(const float4*)&A[(size_t)(m0 + row) * K + k0 + c4 * 4];
        }
        #pragma unroll
        for (int t = 0; t < FB; t++) {
            int idx = tid + 256 * t, row = idx >> 3, c4 = idx & 7;
            int gn = n0 + row;
            const float* bp = (gn < split) ? &B0[(size_t)gn * K]
                                           : &B1[(size_t)(gn - split) * K];
            pb[t] = *(const float4*)&bp[k0 + c4 * 4];
        }
    };
    auto ssts = [&](int buf) {
        const uint32_t Ah = base + buf * BUF;
        const uint32_t Al = Ah + SA;
        const uint32_t Bh = Ah + 2 * SA;
        const uint32_t Bl = Bh + SBB;
        #pragma unroll
        for (int t = 0; t < FA; t++) {
            int idx = tid + 256 * t, row = idx >> 3, c4 = idx & 7;
            uint32_t off = (uint32_t)(row * ROW_B + c4 * 8);
            uint32_t h0, l0, h1, l1;
            split2(pa[t].x, pa[t].y, h0, l0);
            split2(pa[t].z, pa[t].w, h1, l1);
            sts64(Ah + off, h0, h1);
            sts64(Al + off, l0, l1);
        }
        #pragma unroll
        for (int t = 0; t < FB; t++) {
            int idx = tid + 256 * t, row = idx >> 3, c4 = idx & 7;
            uint32_t off = (uint32_t)(row * ROW_B + c4 * 8);
            uint32_t h0, l0, h1, l1;
            split2(pb[t].x, pb[t].y, h0, l0);
            split2(pb[t].z, pb[t].w, h1, l1);
            sts64(Bh + off, h0, h1);
            sts64(Bl + off, l0, l1);
        }
    };
    auto compute = [&](int buf) {
        const uint32_t Ah = base + buf * BUF;
        const uint32_t Bh = Ah + 2 * SA;
        #pragma unroll
        for (int ks = 0; ks < 2; ks++) {
            uint32_t ah[MFRAG][4], al[MFRAG][4];
            uint32_t bh[NFRAG][2], bl[NFRAG][2];
            const uint32_t a_off =
                (uint32_t)((lane & 15) * ROW_B + (lane >> 4) * 16 + ks * 32);
            #pragma unroll
            for (int mf = 0; mf < MFRAG; mf++) {
                uint32_t ad = Ah + (uint32_t)((wm * WM_ + mf * 16) * ROW_B) + a_off;
                ldm_x4(ah[mf][0], ah[mf][1], ah[mf][2], ah[mf][3], ad);
                ldm_x4(al[mf][0], al[mf][1], al[mf][2], al[mf][3], ad + SA);
            }
            const uint32_t b_off =
                (uint32_t)(((lane & 7) + ((lane >> 4) & 1) * 8) * ROW_B
                           + ((lane >> 3) & 1) * 16 + ks * 32);
            #pragma unroll
            for (int nf2 = 0; nf2 < NFRAG / 2; nf2++) {
                uint32_t bd = Bh + (uint32_t)((wn * WN_ + nf2 * 16) * ROW_B) + b_off;
                ldm_x4(bh[2 * nf2][0], bh[2 * nf2][1],
                       bh[2 * nf2 + 1][0], bh[2 * nf2 + 1][1], bd);
                ldm_x4(bl[2 * nf2][0], bl[2 * nf2][1],
                       bl[2 * nf2 + 1][0], bl[2 * nf2 + 1][1], bd + SBB);
            }
            #pragma unroll
            for (int mf = 0; mf < MFRAG; mf++)
                #pragma unroll
                for (int nf = 0; nf < NFRAG; nf++) {
                    mma_bf16(acc[mf][nf], ah[mf], bh[nf]);
                    mma_bf16(acc[mf][nf], ah[mf], bl[nf]);
                    mma_bf16(acc[mf][nf], al[mf], bh[nf]);
                }
        }
    };

    gload(0);
    ssts(0);
    if (nch > 1) gload(1);
    __syncthreads();
    for (int ch = 0; ch < nch; ch++) {
        compute(ch & 1);
        if (ch + 1 < nch) {
            ssts((ch + 1) & 1);
            if (ch + 2 < nch) gload(ch + 2);
        }
        __syncthreads();
    }

    const int g = lane >> 2, tig = lane & 3;
    #pragma unroll
    for (int mf = 0; mf < MFRAG; mf++) {
        const int r0 = m0 + wm * WM_ + mf * 16 + g;
        #pragma unroll
        for (int nf = 0; nf < NFRAG; nf++) {
            const int cN = n0 + wn * WN_ + nf * 8 + tig * 2;
            const float b0v = (cN < split) ? bias0[cN] : bias1[cN - split];
            const float b1v = (cN + 1 < split) ? bias0[cN + 1] : bias1[cN + 1 - split];
            float2 v0 = make_float2(acc[mf][nf][0] + b0v, acc[mf][nf][1] + b1v);
            float2 v1 = make_float2(acc[mf][nf][2] + b0v, acc[mf][nf][3] + b1v);
            *(float2*)&C[(size_t)r0 * NC + cN] = v0;
            *(float2*)&C[(size_t)(r0 + 8) * NC + cN] = v1;
        }
    }
}

// ===========================================================================
// Tensor-core causal multiquery flash attention (FA2-style, 3x bf16 split)
//   CTA: 128 q-rows x 1 head, 8 warps x 16 rows. 64-key tiles.
//   S = Qh*Kh + Qh*Kl + Ql*Kh ; online softmax in fp32 fragments;
//   O += Ph*Vh + Pl*Vh + Ph*Vl (P packed from S accum regs; V via ldmatrix.trans)
// ===========================================================================
#define AROW 144   // smem row stride (64 bf16 = 128B + 16B pad)

__global__ void __launch_bounds__(256, 1)
attn_fa_tc(const float* __restrict__ qg, const float* __restrict__ kv,
           float* __restrict__ ob) {
    __shared__ char smbuf[4 * 64 * AROW];   // 36864 B
    const uint32_t sb = smem_u32(smbuf);
    const uint32_t Kh = sb, Kl = sb + 64 * AROW;
    const uint32_t Vh = sb + 2 * 64 * AROW, Vl = sb + 3 * 64 * AROW;
    const uint32_t Qh = sb, Ql = sb + 2 * 64 * AROW;  // staging alias (pre-loop)

    const int tid  = threadIdx.x;
    const int w    = tid >> 5;
    const int lane = tid & 31;
    const int qb   = (int)gridDim.x - 1 - (int)blockIdx.x;  // heavy blocks first
    const int h    = blockIdx.y;
    const int Rg   = qb * 128 + w * 16;   // warp's global q-row base

    // ---- Stage Q (scaled by 1/8), split hi/lo ----
    #pragma unroll
    for (int t = 0; t < 8; t++) {
        int idx = tid + 256 * t;          // 128 rows * 16 float4
        int row = idx >> 4, c4 = idx & 15;
        float4 v = *(const float4*)&qg[(size_t)(qb * 128 + row) * EMB + h * HD + c4 * 4];
        v.x *= 0.125f; v.y *= 0.125f; v.z *= 0.125f; v.w *= 0.125f;
        uint32_t h0, l0, h1, l1;
        split2(v.x, v.y, h0, l0);
        split2(v.z, v.w, h1, l1);
        uint32_t off = (uint32_t)(row * AROW + c4 * 8);
        sts64(Qh + off, h0, h1);
        sts64(Ql + off, l0, l1);
    }
    __syncthreads();

    // ---- Persistent Q fragments: 4 k16-blocks, hi+lo ----
    uint32_t qfh[4][4], qfl[4][4];
    {
        const uint32_t qa = (uint32_t)((w * 16 + (lane & 15)) * AROW + (lane >> 4) * 16);
        #pragma unroll
        for (int ks = 0; ks < 4; ks++) {
            ldm_x4(qfh[ks][0], qfh[ks][1], qfh[ks][2], qfh[ks][3], Qh + qa + ks * 32);
            ldm_x4(qfl[ks][0], qfl[ks][1], qfl[ks][2], qfl[ks][3], Ql + qa + ks * 32);
        }
    }
    __syncthreads();

    float m0 = -1e30f, m1 = -1e30f, l0 = 0.f, l1 = 0.f;
    float O[8][4] = {};

    const int nt = 2 * (qb + 1);
    for (int t = 0; t < nt; t++) {
        const int k0 = t * 64;

        // ---- Stage K/V tile (64 rows x 128 floats), split hi/lo ----
        #pragma unroll
        for (int it = 0; it < 8; it++) {
            int idx = tid + 256 * it;
            int row = idx >> 5, c4 = idx & 31;
            float4 val = *(const float4*)&kv[(size_t)(k0 + row) * 128 + c4 * 4];
            uint32_t h0, lo0, h1, lo1;
            split2(val.x, val.y, h0, lo0);
            split2(val.z, val.w, h1, lo1);
            uint32_t off = (uint32_t)(row * AROW + (c4 & 15) * 8);
            if (c4 < 16) { sts64(Kh + off, h0, h1); sts64(Kl + off, lo0, lo1); }
            else         { sts64(Vh + off, h0, h1); sts64(Vl + off, lo0, lo1); }
        }
        __syncthreads();

        if (k0 <= Rg + 15) {   // warp not fully masked
            // ---- S = Q K^T (3-split) ----
            float S[8][4] = {};
            #pragma unroll
            for (int kb = 0; kb < 4; kb++) {
                uint32_t bh[8][2], bl[8][2];
                #pragma unroll
                for (int ng = 0; ng < 4; ng++) {
                    uint32_t boff = (uint32_t)(
                        (ng * 16 + (lane & 7) + ((lane >> 4) & 1) * 8) * AROW
                        + ((lane >> 3) & 1) * 16 + kb * 32);
                    ldm_x4(bh[2 * ng][0], bh[2 * ng][1],
                           bh[2 * ng + 1][0], bh[2 * ng + 1][1], Kh + boff);
                    ldm_x4(bl[2 * ng][0], bl[2 * ng][1],
                           bl[2 * ng + 1][0], bl[2 * ng + 1][1], Kl + boff);
                }
                #pragma unroll
                for (int nf = 0; nf < 8; nf++) {
                    mma_bf16(S[nf], qfh[kb], bh[nf]);
                    mma_bf16(S[nf], qfh[kb], bl[nf]);
                    mma_bf16(S[nf], qfl[kb], bh[nf]);
                }
            }

            const int r0_ = Rg + (lane >> 2);
            const int r1_ = r0_ + 8;

            // ---- Causal mask on diagonal tiles ----
            if (k0 + 63 > Rg) {
                #pragma unroll
                for (int nf = 0; nf < 8; nf++) {
                    int key = k0 + nf * 8 + (lane & 3) * 2;
                    if (key     > r0_) S[nf][0] = -1e30f;
                    if (key + 1 > r0_) S[nf][1] = -1e30f;
                    if (key     > r1_) S[nf][2] = -1e30f;
                    if (key + 1 > r1_) S[nf][3] = -1e30f;
                }
            }

            // ---- Online softmax ----
            float mx0 = -1e30f, mx1 = -1e30f;
            #pragma unroll
            for (int nf = 0; nf < 8; nf++) {
                mx0 = fmaxf(mx0, fmaxf(S[nf][0], S[nf][1]));
                mx1 = fmaxf(mx1, fmaxf(S[nf][2], S[nf][3]));
            }
            mx0 = fmaxf(mx0, __shfl_xor_sync(0xFFFFFFFFu, mx0, 1));
            mx0 = fmaxf(mx0, __shfl_xor_sync(0xFFFFFFFFu, mx0, 2));
            mx1 = fmaxf(mx1, __shfl_xor_sync(0xFFFFFFFFu, mx1, 1));
            mx1 = fmaxf(mx1, __shfl_xor_sync(0xFFFFFFFFu, mx1, 2));

            const float nm0 = fmaxf(m0, mx0);
            const float nm1 = fmaxf(m1, mx1);
            const float c0 = __expf(m0 - nm0);
            const float c1 = __expf(m1 - nm1);
            m0 = nm0; m1 = nm1;

            float ps0 = 0.f, ps1 = 0.f;
            #pragma unroll
            for (int nf = 0; nf < 8; nf++) {
                S[nf][0] = __expf(S[nf][0] - nm0);
                S[nf][1] = __expf(S[nf][1] - nm0);
                S[nf][2] = __expf(S[nf][2] - nm1);
                S[nf][3] = __expf(S[nf][3] - nm1);
                ps0 += S[nf][0] + S[nf][1];
                ps1 += S[nf][2] + S[nf][3];
            }
            ps0 += __shfl_xor_sync(0xFFFFFFFFu, ps0, 1);
            ps0 += __shfl_xor_sync(0xFFFFFFFFu, ps0, 2);
            ps1 += __shfl_xor_sync(0xFFFFFFFFu, ps1, 1);
            ps1 += __shfl_xor_sync(0xFFFFFFFFu, ps1, 2);
            l0 = l0 * c0 + ps0;
            l1 = l1 * c1 + ps1;
            #pragma unroll
            for (int nf = 0; nf < 8; nf++) {
                O[nf][0] *= c0; O[nf][1] *= c0;
                O[nf][2] *= c1; O[nf][3] *= c1;
            }

            // ---- O += P V (3-split; P packed from S regs) ----
            #pragma unroll
            for (int kb = 0; kb < 4; kb++) {
                uint32_t ah[4], al[4];
                split2(S[2 * kb][0],     S[2 * kb][1],     ah[0], al[0]);
                split2(S[2 * kb][2],     S[2 * kb][3],     ah[1], al[1]);
                split2(S[2 * kb + 1][0], S[2 * kb + 1][1], ah[2], al[2]);
                split2(S[2 * kb + 1][2], S[2 * kb + 1][3], ah[3], al[3]);

                uint32_t vh[8][2], vl[8][2];
                #pragma unroll
                for (int ng = 0; ng < 4; ng++) {
                    uint32_t voff = (uint32_t)(
                        (kb * 16 + (lane & 15)) * AROW
                        + (ng * 16 + (lane >> 4) * 8) * 2);
                    ldm_x4_t(vh[2 * ng][0], vh[2 * ng][1],
                             vh[2 * ng + 1][0], vh[2 * ng + 1][1], Vh + voff);
                    ldm_x4_t(vl[2 * ng][0], vl[2 * ng][1],
                             vl[2 * ng + 1][0], vl[2 * ng + 1][1], Vl + voff);
                }
                #pragma unroll
                for (int nd = 0; nd < 8; nd++) {
                    mma_bf16(O[nd], ah, vh[nd]);
                    mma_bf16(O[nd], al, vh[nd]);
                    mma_bf16(O[nd], ah, vl[nd]);
                }
            }
        }
        __syncthreads();   // compute done before next tile overwrites smem
    }

    // ---- Epilogue: normalize, store ----
    const float inv0 = 1.f / l0;
    const float inv1 = 1.f / l1;
    const int r0_ = Rg + (lane >> 2);
    const int r1_ = r0_ + 8;
    #pragma unroll
    for (int nd = 0; nd < 8; nd++) {
        const int col = h * HD + nd * 8 + (lane & 3) * 2;
        *(float2*)&ob[(size_t)r0_ * EMB + col] =
            make_float2(O[nd][0] * inv0, O[nd][1] * inv0);
        *(float2*)&ob[(size_t)r1_ * EMB + col] =
            make_float2(O[nd][2] * inv1, O[nd][3] * inv1);
    }
}

// ===========================================================================
// Launch
// Inputs: hidden_states, mask, Wq, bq, Wk, bk, Wv, bv, Wo, bo (mask ignored)
// ===========================================================================
extern "C" void kernel_launch(void* const* d_in, const int* in_sizes, int n_in,
                              void* d_out, int out_size) {
    const float* x  = (const float*)d_in[0];
    const float* Wq = (const float*)d_in[2];
    const float* bq = (const float*)d_in[3];
    const float* Wk = (const float*)d_in[4];
    const float* bk = (const float*)d_in[5];
    const float* Wv = (const float*)d_in[6];
    const float* bv = (const float*)d_in[7];
    const float* Wo = (const float*)d_in[8];
    const float* bo = (const float*)d_in[9];
    float* out = (float*)d_out;

    float *q, *kv, *attn;
    cudaGetSymbolAddress((void**)&q, g_q);
    cudaGetSymbolAddress((void**)&kv, g_kv);
    cudaGetSymbolAddress((void**)&attn, g_attn);

    const int SMEM_BIG = 2 * (2 * 128 + 2 * 128) * 80;   // 81920
    const int SMEM_KV  = 2 * (2 * 32 + 2 * 128) * 80;    // 51200
    cudaFuncSetAttribute((const void*)gemm_bf16x3<128, 128, 64>,
                         cudaFuncAttributeMaxDynamicSharedMemorySize, SMEM_BIG);
    cudaFuncSetAttribute((const void*)gemm_bf16x3<32, 128, 16>,
                         cudaFuncAttributeMaxDynamicSharedMemorySize, SMEM_KV);

    const int BIG = 1 << 30;

    // Q projection: [2048,1024] = x @ Wq^T + bq
    gemm_bf16x3<128, 128, 64><<<dim3(EMB / 128, SEQ / 128), 256, SMEM_BIG>>>(
        x, Wq, Wq, bq, bq, BIG, q, EMB, EMB);

    // Fused K|V projection: [2048,128] = x @ concat(Wk,Wv)^T + concat(bk,bv)
    gemm_bf16x3<32, 128, 16><<<dim3(1, SEQ / 32), 256, SMEM_KV>>>(
        x, Wk, Wv, bk, bv, HD, kv, 128, EMB);

    // Tensor-core flash attention (causal, multiquery)
    attn_fa_tc<<<dim3(16, NH), 256>>>(q, kv, attn);

    // Output projection: out = attn @ Wo^T + bo
    gemm_bf16x3<128, 128, 64><<<dim3(EMB / 128, SEQ / 128), 256, SMEM_BIG>>>(
        attn, Wo, Wo, bo, bo, BIG, out, EMB, EMB);
}

// round 6
// speedup vs baseline: 4.2813x; 1.1157x over previous
#include <cuda_runtime.h>
#include <cuda_bf16.h>
#include <stdint.h>

#define SEQ 2048
#define EMB 1024
#define NH  16
#define HD  64

// ---------------------------------------------------------------------------
// Pre-split bf16 scratch (allocation-free rule: __device__ globals)
// ---------------------------------------------------------------------------
__device__ __nv_bfloat16 g_xh[SEQ * EMB],  g_xl[SEQ * EMB];
__device__ __nv_bfloat16 g_wqh[EMB * EMB], g_wql[EMB * EMB];
__device__ __nv_bfloat16 g_woh[EMB * EMB], g_wol[EMB * EMB];
__device__ __nv_bfloat16 g_wkvh[128 * EMB], g_wkvl[128 * EMB];
__device__ float g_bkv[128];
__device__ __nv_bfloat16 g_qh[SEQ * EMB], g_ql[SEQ * EMB];      // scaled q
__device__ __nv_bfloat16 g_kvh[SEQ * 128], g_kvl[SEQ * 128];    // K|V fused
__device__ __nv_bfloat16 g_ah[SEQ * EMB], g_al[SEQ * EMB];      // attn out

// ---------------------------------------------------------------------------
// Helpers (portable sm_80+: ldmatrix, mma.sync, cp.async — NO tcgen05)
// ---------------------------------------------------------------------------
__device__ __forceinline__ uint32_t smem_u32(const void* p) {
    uint32_t a;
    asm("{ .reg .u64 t; cvta.to.shared.u64 t, %1; cvt.u32.u64 %0, t; }"
        : "=r"(a) : "l"(p));
    return a;
}
__device__ __forceinline__ void ldm_x4(uint32_t& r0, uint32_t& r1,
                                       uint32_t& r2, uint32_t& r3, uint32_t a) {
    asm volatile("ldmatrix.sync.aligned.m8n8.x4.shared.b16 {%0,%1,%2,%3}, [%4];"
                 : "=r"(r0), "=r"(r1), "=r"(r2), "=r"(r3) : "r"(a));
}
__device__ __forceinline__ void ldm_x4_t(uint32_t& r0, uint32_t& r1,
                                         uint32_t& r2, uint32_t& r3, uint32_t a) {
    asm volatile("ldmatrix.sync.aligned.m8n8.x4.trans.shared.b16 {%0,%1,%2,%3}, [%4];"
                 : "=r"(r0), "=r"(r1), "=r"(r2), "=r"(r3) : "r"(a));
}
__device__ __forceinline__ void mma_bf16(float* c, const uint32_t* a,
                                         const uint32_t* b) {
    asm volatile(
        "mma.sync.aligned.m16n8k16.row.col.f32.bf16.bf16.f32 "
        "{%0,%1,%2,%3}, {%4,%5,%6,%7}, {%8,%9}, {%0,%1,%2,%3};"
        : "+f"(c[0]), "+f"(c[1]), "+f"(c[2]), "+f"(c[3])
        : "r"(a[0]), "r"(a[1]), "r"(a[2]), "r"(a[3]), "r"(b[0]), "r"(b[1]));
}
__device__ __forceinline__ void split2(float x, float y, uint32_t& h, uint32_t& l) {
    __nv_bfloat16 hx = __float2bfloat16(x);
    __nv_bfloat16 hy = __float2bfloat16(y);
    __nv_bfloat16 lx = __float2bfloat16(x - __bfloat162float(hx));
    __nv_bfloat16 ly = __float2bfloat16(y - __bfloat162float(hy));
    h = ((uint32_t)__bfloat16_as_ushort(hy) << 16) | __bfloat16_as_ushort(hx);
    l = ((uint32_t)__bfloat16_as_ushort(ly) << 16) | __bfloat16_as_ushort(lx);
}
__device__ __forceinline__ void cpa16(uint32_t dst, const void* src) {
    asm volatile("cp.async.cg.shared.global [%0], [%1], 16;"
                 :: "r"(dst), "l"(src) : "memory");
}
#define CP_COMMIT asm volatile("cp.async.commit_group;" ::: "memory")
#define CP_WAIT(n) asm volatile("cp.async.wait_group %0;" :: "n"(n) : "memory")

// ---------------------------------------------------------------------------
// Prep: split fp32 -> bf16 hi/lo (vectorized)
// ---------------------------------------------------------------------------
__global__ void splitk(const float4* __restrict__ src, uint32_t* __restrict__ hi,
                       uint32_t* __restrict__ lo, int n4) {
    int i = blockIdx.x * 256 + threadIdx.x;
    if (i < n4) {
        float4 v = src[i];
        uint32_t h0, l0, h1, l1;
        split2(v.x, v.y, h0, l0);
        split2(v.z, v.w, h1, l1);
        hi[2 * i] = h0; hi[2 * i + 1] = h1;
        lo[2 * i] = l0; lo[2 * i + 1] = l1;
    }
}
__global__ void bias_concat(const float* __restrict__ a, const float* __restrict__ b,
                            float* __restrict__ o) {
    int i = threadIdx.x;
    o[i] = (i < 64) ? a[i] : b[i - 64];
}

// ---------------------------------------------------------------------------
// GEMM v3: pre-split bf16 operands, cp.async 3-stage pipeline, 3-term MMA.
//   C[M,NC] = A @ B^T + bias ; OUT=0: fp32 C ; OUT=1: split bf16 (Ch,Cl)*scale
// ---------------------------------------------------------------------------
template <int BM, int BN, int WN_, int OUT>
__global__ void __launch_bounds__(256)
gemm_pre(const __nv_bfloat16* __restrict__ Ah_g, const __nv_bfloat16* __restrict__ Al_g,
         const __nv_bfloat16* __restrict__ Bh_g, const __nv_bfloat16* __restrict__ Bl_g,
         const float* __restrict__ bias, float* __restrict__ C,
         __nv_bfloat16* __restrict__ Ch, __nv_bfloat16* __restrict__ Cl,
         float scale, int NC, int K) {
    constexpr int WM_   = 32;
    constexpr int MFRAG = 2;
    constexpr int NFRAG = WN_ / 8;
    constexpr int NWN   = BN / WN_;
    constexpr int SA    = BM * 80;
    constexpr int SB    = BN * 80;
    constexpr int STAGE = 2 * SA + 2 * SB;
    constexpr int CA    = BM * 4;       // 16B chunks per A operand tile
    constexpr int CB    = BN * 4;
    constexpr int NIT   = (2 * CA + 2 * CB) / 256;

    extern __shared__ char sm[];
    const uint32_t base = smem_u32(sm);
    const int tid = threadIdx.x;
    const int w = tid >> 5, lane = tid & 31;
    const int wm = w / NWN, wn = w % NWN;
    const int m0 = blockIdx.y * BM, n0 = blockIdx.x * BN;
    const int nch = K / 32;

    auto issue = [&](int ch) {
        const uint32_t st = base + (ch % 3) * STAGE;
        const int k0 = ch * 32;
        #pragma unroll
        for (int i = 0; i < NIT; i++) {
            int c = tid + 256 * i;
            const __nv_bfloat16* src;
            uint32_t dst;
            if (c < CA) {
                int r = c >> 2, p = c & 3;
                src = Ah_g + (size_t)(m0 + r) * K + k0 + p * 8;
                dst = st + r * 80 + p * 16;
            } else if (c < 2 * CA) {
                int cc = c - CA, r = cc >> 2, p = cc & 3;
                src = Al_g + (size_t)(m0 + r) * K + k0 + p * 8;
                dst = st + SA + r * 80 + p * 16;
            } else if (c < 2 * CA + CB) {
                int cc = c - 2 * CA, r = cc >> 2, p = cc & 3;
                src = Bh_g + (size_t)(n0 + r) * K + k0 + p * 8;
                dst = st + 2 * SA + r * 80 + p * 16;
            } else {
                int cc = c - 2 * CA - CB, r = cc >> 2, p = cc & 3;
                src = Bl_g + (size_t)(n0 + r) * K + k0 + p * 8;
                dst = st + 2 * SA + SB + r * 80 + p * 16;
            }
            cpa16(dst, src);
        }
    };

    float acc[MFRAG][NFRAG][4] = {};

    issue(0); CP_COMMIT;
    issue(1); CP_COMMIT;

    for (int ch = 0; ch < nch; ch++) {
        if (ch + 2 < nch)      { issue(ch + 2); CP_COMMIT; CP_WAIT(2); }
        else if (ch + 1 < nch) { CP_WAIT(1); }
        else                   { CP_WAIT(0); }
        __syncthreads();

        const uint32_t st = base + (ch % 3) * STAGE;
        const uint32_t Bhs = st + 2 * SA;
        #pragma unroll
        for (int ks = 0; ks < 2; ks++) {
            uint32_t ah[MFRAG][4], al[MFRAG][4], bh[NFRAG][2], bl[NFRAG][2];
            const uint32_t a_off =
                (uint32_t)((lane & 15) * 80 + (lane >> 4) * 16 + ks * 32);
            #pragma unroll
            for (int mf = 0; mf < MFRAG; mf++) {
                uint32_t ad = st + (uint32_t)((wm * WM_ + mf * 16) * 80) + a_off;
                ldm_x4(ah[mf][0], ah[mf][1], ah[mf][2], ah[mf][3], ad);
                ldm_x4(al[mf][0], al[mf][1], al[mf][2], al[mf][3], ad + SA);
            }
            const uint32_t b_off =
                (uint32_t)(((lane & 7) + ((lane >> 4) & 1) * 8) * 80
                           + ((lane >> 3) & 1) * 16 + ks * 32);
            #pragma unroll
            for (int nf2 = 0; nf2 < NFRAG / 2; nf2++) {
                uint32_t bd = Bhs + (uint32_t)((wn * WN_ + nf2 * 16) * 80) + b_off;
                ldm_x4(bh[2 * nf2][0], bh[2 * nf2][1],
                       bh[2 * nf2 + 1][0], bh[2 * nf2 + 1][1], bd);
                ldm_x4(bl[2 * nf2][0], bl[2 * nf2][1],
                       bl[2 * nf2 + 1][0], bl[2 * nf2 + 1][1], bd + SB);
            }
            #pragma unroll
            for (int mf = 0; mf < MFRAG; mf++)
                #pragma unroll
                for (int nf = 0; nf < NFRAG; nf++) {
                    mma_bf16(acc[mf][nf], ah[mf], bh[nf]);
                    mma_bf16(acc[mf][nf], ah[mf], bl[nf]);
                    mma_bf16(acc[mf][nf], al[mf], bh[nf]);
                }
        }
        __syncthreads();
    }

    // Epilogue
    const int g = lane >> 2, tig = lane & 3;
    #pragma unroll
    for (int mf = 0; mf < MFRAG; mf++) {
        const int r0 = m0 + wm * WM_ + mf * 16 + g;
        #pragma unroll
        for (int nf = 0; nf < NFRAG; nf++) {
            const int cN = n0 + wn * WN_ + nf * 8 + tig * 2;
            const float b0v = bias[cN], b1v = bias[cN + 1];
            if (OUT == 0) {
                *(float2*)&C[(size_t)r0 * NC + cN] =
                    make_float2(acc[mf][nf][0] + b0v, acc[mf][nf][1] + b1v);
                *(float2*)&C[(size_t)(r0 + 8) * NC + cN] =
                    make_float2(acc[mf][nf][2] + b0v, acc[mf][nf][3] + b1v);
            } else {
                uint32_t h0, l0, h1, l1;
                split2((acc[mf][nf][0] + b0v) * scale, (acc[mf][nf][1] + b1v) * scale, h0, l0);
                split2((acc[mf][nf][2] + b0v) * scale, (acc[mf][nf][3] + b1v) * scale, h1, l1);
                *(uint32_t*)&Ch[(size_t)r0 * NC + cN] = h0;
                *(uint32_t*)&Cl[(size_t)r0 * NC + cN] = l0;
                *(uint32_t*)&Ch[(size_t)(r0 + 8) * NC + cN] = h1;
                *(uint32_t*)&Cl[(size_t)(r0 + 8) * NC + cN] = l1;
            }
        }
    }
}

// ---------------------------------------------------------------------------
// Attention v3: pre-split bf16 Q/K/V via cp.async, 2-stage K/V pipeline.
//   CTA: 128 q-rows x 1 head, 8 warps x 16 rows; 64-key tiles; 3-term MMAs.
//   Output written pre-split (attn hi/lo) for O-proj.
// ---------------------------------------------------------------------------
#define AROW 144
#define KVST (4 * 64 * AROW)   // 36864 bytes per stage

__global__ void __launch_bounds__(256, 1)
attn_fa_tc3(const __nv_bfloat16* __restrict__ qh, const __nv_bfloat16* __restrict__ ql,
            const __nv_bfloat16* __restrict__ kvh, const __nv_bfloat16* __restrict__ kvl,
            __nv_bfloat16* __restrict__ oh, __nv_bfloat16* __restrict__ ol) {
    extern __shared__ char smbuf[];            // 2 * KVST
    const uint32_t sb = smem_u32(smbuf);

    const int tid  = threadIdx.x;
    const int w    = tid >> 5;
    const int lane = tid & 31;
    const int qb   = (int)gridDim.x - 1 - (int)blockIdx.x;  // heavy blocks first
    const int h    = blockIdx.y;
    const int Rg   = qb * 128 + w * 16;

    // ---- Stage Q (pre-scaled, pre-split) into stage-0/1 region (aliased) ----
    {
        const uint32_t Qlo = sb + 128 * AROW;
        #pragma unroll
        for (int i = 0; i < 8; i++) {
            int c = tid + 256 * i;              // 0..2047
            int half = c >> 10;
            int cc = c & 1023;
            int row = cc >> 3, p = cc & 7;
            const __nv_bfloat16* src = (half ? ql : qh)
                + (size_t)(qb * 128 + row) * EMB + h * HD + p * 8;
            uint32_t dst = (half ? Qlo : sb) + row * AROW + p * 16;
            cpa16(dst, src);
        }
        CP_COMMIT; CP_WAIT(0);
        __syncthreads();
    }

    // ---- Persistent Q fragments ----
    uint32_t qfh[4][4], qfl[4][4];
    {
        const uint32_t qa = (uint32_t)((w * 16 + (lane & 15)) * AROW + (lane >> 4) * 16);
        #pragma unroll
        for (int ks = 0; ks < 4; ks++) {
            ldm_x4(qfh[ks][0], qfh[ks][1], qfh[ks][2], qfh[ks][3], sb + qa + ks * 32);
            ldm_x4(qfl[ks][0], qfl[ks][1], qfl[ks][2], qfl[ks][3],
                   sb + 128 * AROW + qa + ks * 32);
        }
    }
    __syncthreads();

    auto issueKV = [&](int t) {
        const uint32_t st = sb + (t & 1) * KVST;
        const int k0 = t * 64;
        #pragma unroll
        for (int i = 0; i < 8; i++) {
            int c = tid + 256 * i;              // 0..2047
            int row = c >> 5, q = c & 31;
            int sec = q >> 3, p = q & 7;        // 0:Kh 1:Kl 2:Vh 3:Vl
            const __nv_bfloat16* src = ((sec & 1) ? kvl : kvh)
                + (size_t)(k0 + row) * 128 + ((sec >> 1) ? 64 : 0) + p * 8;
            uint32_t dst = st + sec * (64 * AROW) + row * AROW + p * 16;
            cpa16(dst, src);
        }
    };

    float m0 = -1e30f, m1 = -1e30f, l0 = 0.f, l1 = 0.f;
    float O[8][4] = {};
    const int nt = 2 * (qb + 1);

    issueKV(0); CP_COMMIT;
    for (int t = 0; t < nt; t++) {
        if (t + 1 < nt) { issueKV(t + 1); CP_COMMIT; CP_WAIT(1); }
        else            { CP_WAIT(0); }
        __syncthreads();

        const uint32_t st = sb + (t & 1) * KVST;
        const uint32_t Kh = st, Kl = st + 64 * AROW;
        const uint32_t Vh = st + 2 * 64 * AROW, Vl = st + 3 * 64 * AROW;
        const int k0 = t * 64;

        if (k0 <= Rg + 15) {
            // ---- S = Q K^T (3-term) ----
            float S[8][4] = {};
            #pragma unroll
            for (int kb = 0; kb < 4; kb++) {
                uint32_t bh[8][2], bl[8][2];
                #pragma unroll
                for (int ng = 0; ng < 4; ng++) {
                    uint32_t boff = (uint32_t)(
                        (ng * 16 + (lane & 7) + ((lane >> 4) & 1) * 8) * AROW
                        + ((lane >> 3) & 1) * 16 + kb * 32);
                    ldm_x4(bh[2 * ng][0], bh[2 * ng][1],
                           bh[2 * ng + 1][0], bh[2 * ng + 1][1], Kh + boff);
                    ldm_x4(bl[2 * ng][0], bl[2 * ng][1],
                           bl[2 * ng + 1][0], bl[2 * ng + 1][1], Kl + boff);
                }
                #pragma unroll
                for (int nf = 0; nf < 8; nf++) {
                    mma_bf16(S[nf], qfh[kb], bh[nf]);
                    mma_bf16(S[nf], qfh[kb], bl[nf]);
                    mma_bf16(S[nf], qfl[kb], bh[nf]);
                }
            }

            const int r0_ = Rg + (lane >> 2);
            const int r1_ = r0_ + 8;

            // ---- Causal mask (diagonal tiles only) ----
            if (k0 + 63 > Rg) {
                #pragma unroll
                for (int nf = 0; nf < 8; nf++) {
                    int key = k0 + nf * 8 + (lane & 3) * 2;
                    if (key     > r0_) S[nf][0] = -1e30f;
                    if (key + 1 > r0_) S[nf][1] = -1e30f;
                    if (key     > r1_) S[nf][2] = -1e30f;
                    if (key + 1 > r1_) S[nf][3] = -1e30f;
                }
            }

            // ---- Online softmax ----
            float mx0 = -1e30f, mx1 = -1e30f;
            #pragma unroll
            for (int nf = 0; nf < 8; nf++) {
                mx0 = fmaxf(mx0, fmaxf(S[nf][0], S[nf][1]));
                mx1 = fmaxf(mx1, fmaxf(S[nf][2], S[nf][3]));
            }
            mx0 = fmaxf(mx0, __shfl_xor_sync(0xFFFFFFFFu, mx0, 1));
            mx0 = fmaxf(mx0, __shfl_xor_sync(0xFFFFFFFFu, mx0, 2));
            mx1 = fmaxf(mx1, __shfl_xor_sync(0xFFFFFFFFu, mx1, 1));
            mx1 = fmaxf(mx1, __shfl_xor_sync(0xFFFFFFFFu, mx1, 2));

            const float nm0 = fmaxf(m0, mx0);
            const float nm1 = fmaxf(m1, mx1);
            const float c0 = __expf(m0 - nm0);
            const float c1 = __expf(m1 - nm1);
            m0 = nm0; m1 = nm1;

            float ps0 = 0.f, ps1 = 0.f;
            #pragma unroll
            for (int nf = 0; nf < 8; nf++) {
                S[nf][0] = __expf(S[nf][0] - nm0);
                S[nf][1] = __expf(S[nf][1] - nm0);
                S[nf][2] = __expf(S[nf][2] - nm1);
                S[nf][3] = __expf(S[nf][3] - nm1);
                ps0 += S[nf][0] + S[nf][1];
                ps1 += S[nf][2] + S[nf][3];
            }
            ps0 += __shfl_xor_sync(0xFFFFFFFFu, ps0, 1);
            ps0 += __shfl_xor_sync(0xFFFFFFFFu, ps0, 2);
            ps1 += __shfl_xor_sync(0xFFFFFFFFu, ps1, 1);
            ps1 += __shfl_xor_sync(0xFFFFFFFFu, ps1, 2);
            l0 = l0 * c0 + ps0;
            l1 = l1 * c1 + ps1;
            #pragma unroll
            for (int nf = 0; nf < 8; nf++) {
                O[nf][0] *= c0; O[nf][1] *= c0;
                O[nf][2] *= c1; O[nf][3] *= c1;
            }

            // ---- O += P V (3-term; P split from S regs) ----
            #pragma unroll
            for (int kb = 0; kb < 4; kb++) {
                uint32_t ah[4], al[4];
                split2(S[2 * kb][0],     S[2 * kb][1],     ah[0], al[0]);
                split2(S[2 * kb][2],     S[2 * kb][3],     ah[1], al[1]);
                split2(S[2 * kb + 1][0], S[2 * kb + 1][1], ah[2], al[2]);
                split2(S[2 * kb + 1][2], S[2 * kb + 1][3], ah[3], al[3]);

                uint32_t vh[8][2], vl[8][2];
                #pragma unroll
                for (int ng = 0; ng < 4; ng++) {
                    uint32_t voff = (uint32_t)(
                        (kb * 16 + (lane & 15)) * AROW
                        + (ng * 16 + (lane >> 4) * 8) * 2);
                    ldm_x4_t(vh[2 * ng][0], vh[2 * ng][1],
                             vh[2 * ng + 1][0], vh[2 * ng + 1][1], Vh + voff);
                    ldm_x4_t(vl[2 * ng][0], vl[2 * ng][1],
                             vl[2 * ng + 1][0], vl[2 * ng + 1][1], Vl + voff);
                }
                #pragma unroll
                for (int nd = 0; nd < 8; nd++) {
                    mma_bf16(O[nd], ah, vh[nd]);
                    mma_bf16(O[nd], al, vh[nd]);
                    mma_bf16(O[nd], ah, vl[nd]);
                }
            }
        }
        __syncthreads();
    }

    // ---- Epilogue: normalize, split, store bf16 hi/lo ----
    const float inv0 = 1.f / l0;
    const float inv1 = 1.f / l1;
    const int r0_ = Rg + (lane >> 2);
    const int r1_ = r0_ + 8;
    #pragma unroll
    for (int nd = 0; nd < 8; nd++) {
        const int col = h * HD + nd * 8 + (lane & 3) * 2;
        uint32_t h0, l0v, h1, l1v;
        split2(O[nd][0] * inv0, O[nd][1] * inv0, h0, l0v);
        split2(O[nd][2] * inv1, O[nd][3] * inv1, h1, l1v);
        *(uint32_t*)&oh[(size_t)r0_ * EMB + col] = h0;
        *(uint32_t*)&ol[(size_t)r0_ * EMB + col] = l0v;
        *(uint32_t*)&oh[(size_t)r1_ * EMB + col] = h1;
        *(uint32_t*)&ol[(size_t)r1_ * EMB + col] = l1v;
    }
}

// ===========================================================================
// Launch
// Inputs: hidden_states, mask, Wq, bq, Wk, bk, Wv, bv, Wo, bo (mask ignored)
// ===========================================================================
extern "C" void kernel_launch(void* const* d_in, const int* in_sizes, int n_in,
                              void* d_out, int out_size) {
    const float* x  = (const float*)d_in[0];
    const float* Wq = (const float*)d_in[2];
    const float* bq = (const float*)d_in[3];
    const float* Wk = (const float*)d_in[4];
    const float* bk = (const float*)d_in[5];
    const float* Wv = (const float*)d_in[6];
    const float* bv = (const float*)d_in[7];
    const float* Wo = (const float*)d_in[8];
    const float* bo = (const float*)d_in[9];
    float* out = (float*)d_out;

    __nv_bfloat16 *xh, *xl, *wqh, *wql, *woh, *wol, *wkvh, *wkvl;
    __nv_bfloat16 *qh, *ql, *kvh, *kvl, *ah, *al;
    float* bkv;
    cudaGetSymbolAddress((void**)&xh, g_xh);   cudaGetSymbolAddress((void**)&xl, g_xl);
    cudaGetSymbolAddress((void**)&wqh, g_wqh); cudaGetSymbolAddress((void**)&wql, g_wql);
    cudaGetSymbolAddress((void**)&woh, g_woh); cudaGetSymbolAddress((void**)&wol, g_wol);
    cudaGetSymbolAddress((void**)&wkvh, g_wkvh); cudaGetSymbolAddress((void**)&wkvl, g_wkvl);
    cudaGetSymbolAddress((void**)&qh, g_qh);   cudaGetSymbolAddress((void**)&ql, g_ql);
    cudaGetSymbolAddress((void**)&kvh, g_kvh); cudaGetSymbolAddress((void**)&kvl, g_kvl);
    cudaGetSymbolAddress((void**)&ah, g_ah);   cudaGetSymbolAddress((void**)&al, g_al);
    cudaGetSymbolAddress((void**)&bkv, g_bkv);

    const int SMEM_BIG = 3 * (2 * 128 + 2 * 128) * 80;   // 122880
    const int SMEM_KV  = 3 * (2 * 32 + 2 * 128) * 80;    // 76800
    const int SMEM_ATT = 2 * KVST;                       // 73728
    cudaFuncSetAttribute((const void*)gemm_pre<128, 128, 64, 1>,
                         cudaFuncAttributeMaxDynamicSharedMemorySize, SMEM_BIG);
    cudaFuncSetAttribute((const void*)gemm_pre<128, 128, 64, 0>,
                         cudaFuncAttributeMaxDynamicSharedMemorySize, SMEM_BIG);
    cudaFuncSetAttribute((const void*)gemm_pre<32, 128, 16, 1>,
                         cudaFuncAttributeMaxDynamicSharedMemorySize, SMEM_KV);
    cudaFuncSetAttribute((const void*)attn_fa_tc3,
                         cudaFuncAttributeMaxDynamicSharedMemorySize, SMEM_ATT);

    // ---- Prep: split inputs/weights once ----
    splitk<<<SEQ * EMB / 1024, 256>>>((const float4*)x, (uint32_t*)xh, (uint32_t*)xl,
                                      SEQ * EMB / 4);
    splitk<<<EMB * EMB / 1024, 256>>>((const float4*)Wq, (uint32_t*)wqh, (uint32_t*)wql,
                                      EMB * EMB / 4);
    splitk<<<EMB * EMB / 1024, 256>>>((const float4*)Wo, (uint32_t*)woh, (uint32_t*)wol,
                                      EMB * EMB / 4);
    splitk<<<HD * EMB / 1024, 256>>>((const float4*)Wk, (uint32_t*)wkvh, (uint32_t*)wkvl,
                                     HD * EMB / 4);
    splitk<<<HD * EMB / 1024, 256>>>((const float4*)Wv,
                                     (uint32_t*)wkvh + HD * EMB / 2,
                                     (uint32_t*)wkvl + HD * EMB / 2, HD * EMB / 4);
    bias_concat<<<1, 128>>>(bk, bv, bkv);

    // ---- Q projection -> scaled, pre-split q ----
    gemm_pre<128, 128, 64, 1><<<dim3(8, 16), 256, SMEM_BIG>>>(
        xh, xl, wqh, wql, bq, nullptr, qh, ql, 0.125f, EMB, EMB);

    // ---- Fused K|V projection -> pre-split kv ----
    gemm_pre<32, 128, 16, 1><<<dim3(1, 64), 256, SMEM_KV>>>(
        xh, xl, wkvh, wkvl, bkv, nullptr, kvh, kvl, 1.f, 128, EMB);

    // ---- Flash attention -> pre-split attn ----
    attn_fa_tc3<<<dim3(16, NH), 256, SMEM_ATT>>>(qh, ql, kvh, kvl, ah, al);

    // ---- Output projection -> fp32 out ----
    gemm_pre<128, 128, 64, 0><<<dim3(8, 16), 256, SMEM_BIG>>>(
        ah, al, woh, wol, bo, out, nullptr, nullptr, 1.f, EMB, EMB);
}

// round 7
// speedup vs baseline: 5.0511x; 1.1798x over previous
#include <cuda_runtime.h>
#include <cuda_bf16.h>
#include <stdint.h>

#define SEQ 2048
#define EMB 1024
#define NH  16
#define HD  64
#define NALL 1152   // Wq(1024) | Wk(64) | Wv(64) rows

// ---------------------------------------------------------------------------
// Pre-split bf16 scratch + attention partials (allocation-free rule)
// ---------------------------------------------------------------------------
__device__ __nv_bfloat16 g_xh[SEQ * EMB],  g_xl[SEQ * EMB];
__device__ __nv_bfloat16 g_wallh[NALL * EMB], g_walll[NALL * EMB];
__device__ __nv_bfloat16 g_woh[EMB * EMB], g_wol[EMB * EMB];
__device__ float g_ball[NALL];
__device__ __nv_bfloat16 g_qh[SEQ * EMB], g_ql[SEQ * EMB];      // scaled q
__device__ __nv_bfloat16 g_kvh[SEQ * 128], g_kvl[SEQ * 128];    // K|V fused
__device__ __nv_bfloat16 g_ah[SEQ * EMB], g_al[SEQ * EMB];      // attn out
__device__ float g_pO[2 * SEQ * NH * HD];                       // split partials
__device__ float g_pm[2 * SEQ * NH];
__device__ float g_pl[2 * SEQ * NH];

// ---------------------------------------------------------------------------
// Helpers (portable sm_80+: ldmatrix, mma.sync, cp.async — NO tcgen05)
// ---------------------------------------------------------------------------
__device__ __forceinline__ uint32_t smem_u32(const void* p) {
    uint32_t a;
    asm("{ .reg .u64 t; cvta.to.shared.u64 t, %1; cvt.u32.u64 %0, t; }"
        : "=r"(a) : "l"(p));
    return a;
}
__device__ __forceinline__ void ldm_x4(uint32_t& r0, uint32_t& r1,
                                       uint32_t& r2, uint32_t& r3, uint32_t a) {
    asm volatile("ldmatrix.sync.aligned.m8n8.x4.shared.b16 {%0,%1,%2,%3}, [%4];"
                 : "=r"(r0), "=r"(r1), "=r"(r2), "=r"(r3) : "r"(a));
}
__device__ __forceinline__ void ldm_x4_t(uint32_t& r0, uint32_t& r1,
                                         uint32_t& r2, uint32_t& r3, uint32_t a) {
    asm volatile("ldmatrix.sync.aligned.m8n8.x4.trans.shared.b16 {%0,%1,%2,%3}, [%4];"
                 : "=r"(r0), "=r"(r1), "=r"(r2), "=r"(r3) : "r"(a));
}
__device__ __forceinline__ void mma_bf16(float* c, const uint32_t* a,
                                         const uint32_t* b) {
    asm volatile(
        "mma.sync.aligned.m16n8k16.row.col.f32.bf16.bf16.f32 "
        "{%0,%1,%2,%3}, {%4,%5,%6,%7}, {%8,%9}, {%0,%1,%2,%3};"
        : "+f"(c[0]), "+f"(c[1]), "+f"(c[2]), "+f"(c[3])
        : "r"(a[0]), "r"(a[1]), "r"(a[2]), "r"(a[3]), "r"(b[0]), "r"(b[1]));
}
__device__ __forceinline__ void split2(float x, float y, uint32_t& h, uint32_t& l) {
    __nv_bfloat16 hx = __float2bfloat16(x);
    __nv_bfloat16 hy = __float2bfloat16(y);
    __nv_bfloat16 lx = __float2bfloat16(x - __bfloat162float(hx));
    __nv_bfloat16 ly = __float2bfloat16(y - __bfloat162float(hy));
    h = ((uint32_t)__bfloat16_as_ushort(hy) << 16) | __bfloat16_as_ushort(hx);
    l = ((uint32_t)__bfloat16_as_ushort(ly) << 16) | __bfloat16_as_ushort(lx);
}
__device__ __forceinline__ void cpa16(uint32_t dst, const void* src) {
    asm volatile("cp.async.cg.shared.global [%0], [%1], 16;"
                 :: "r"(dst), "l"(src) : "memory");
}
#define CP_COMMIT asm volatile("cp.async.commit_group;" ::: "memory")
#define CP_WAIT(n) asm volatile("cp.async.wait_group %0;" :: "n"(n) : "memory")

// ---------------------------------------------------------------------------
// Fused prep: split x, Wq|Wk|Wv (into wall), Wo; concat biases. One launch.
// ---------------------------------------------------------------------------
__global__ void prep_all(const float4* __restrict__ x,
                         const float4* __restrict__ wq, const float4* __restrict__ wk,
                         const float4* __restrict__ wv, const float4* __restrict__ wo,
                         const float* __restrict__ bq, const float* __restrict__ bk,
                         const float* __restrict__ bv) {
    const int b = blockIdx.x;
    if (b == 4224) {   // bias concat
        for (int i = threadIdx.x; i < NALL; i += 256) {
            g_ball[i] = (i < 1024) ? bq[i] : (i < 1088) ? bk[i - 1024] : bv[i - 1088];
        }
        return;
    }
    const float4* src;
    uint32_t *hi, *lo;
    int i;   // float4 index within segment
    if (b < 2048)      { src = x;  hi = (uint32_t*)g_xh;    lo = (uint32_t*)g_xl;
                         i = b * 256 + threadIdx.x; }
    else if (b < 3072) { src = wq; hi = (uint32_t*)g_wallh; lo = (uint32_t*)g_walll;
                         i = (b - 2048) * 256 + threadIdx.x; }
    else if (b < 4096) { src = wo; hi = (uint32_t*)g_woh;   lo = (uint32_t*)g_wol;
                         i = (b - 3072) * 256 + threadIdx.x; }
    else if (b < 4160) { src = wk; hi = (uint32_t*)g_wallh + 524288;
                         lo = (uint32_t*)g_walll + 524288;
                         i = (b - 4096) * 256 + threadIdx.x; }
    else               { src = wv; hi = (uint32_t*)g_wallh + 557056;
                         lo = (uint32_t*)g_walll + 557056;
                         i = (b - 4160) * 256 + threadIdx.x; }
    float4 v = src[i];
    uint32_t h0, l0, h1, l1;
    split2(v.x, v.y, h0, l0);
    split2(v.z, v.w, h1, l1);
    hi[2 * i] = h0; hi[2 * i + 1] = h1;
    lo[2 * i] = l0; lo[2 * i + 1] = l1;
}

// ---------------------------------------------------------------------------
// GEMM: pre-split bf16 operands, cp.async 3-stage pipeline, 3-term MMA.
//   OUT=0: fp32 C = A@B^T + bias (stride NC)
//   OUT=1: fused QKV epilogue — cols <1024 -> (qh,ql)*0.125 stride 1024;
//          cols >=1024 -> (kvh,kvl) stride 128.
// ---------------------------------------------------------------------------
template <int BM, int BN, int WN_, int OUT>
__global__ void __launch_bounds__(256)
gemm_pre(const __nv_bfloat16* __restrict__ Ah_g, const __nv_bfloat16* __restrict__ Al_g,
         const __nv_bfloat16* __restrict__ Bh_g, const __nv_bfloat16* __restrict__ Bl_g,
         const float* __restrict__ bias, float* __restrict__ C,
         __nv_bfloat16* __restrict__ Qh, __nv_bfloat16* __restrict__ Ql,
         __nv_bfloat16* __restrict__ KVh, __nv_bfloat16* __restrict__ KVl,
         int NC, int K) {
    constexpr int WM_   = 32;
    constexpr int MFRAG = 2;
    constexpr int NFRAG = WN_ / 8;
    constexpr int NWN   = BN / WN_;
    constexpr int SA    = BM * 80;
    constexpr int SB    = BN * 80;
    constexpr int STAGE = 2 * SA + 2 * SB;
    constexpr int CA    = BM * 4;
    constexpr int CB    = BN * 4;
    constexpr int NIT   = (2 * CA + 2 * CB) / 256;

    extern __shared__ char sm[];
    const uint32_t base = smem_u32(sm);
    const int tid = threadIdx.x;
    const int w = tid >> 5, lane = tid & 31;
    const int wm = w / NWN, wn = w % NWN;
    const int m0 = blockIdx.y * BM, n0 = blockIdx.x * BN;
    const int nch = K / 32;

    auto issue = [&](int ch) {
        const uint32_t st = base + (ch % 3) * STAGE;
        const int k0 = ch * 32;
        #pragma unroll
        for (int i = 0; i < NIT; i++) {
            int c = tid + 256 * i;
            const __nv_bfloat16* src;
            uint32_t dst;
            if (c < CA) {
                int r = c >> 2, p = c & 3;
                src = Ah_g + (size_t)(m0 + r) * K + k0 + p * 8;
                dst = st + r * 80 + p * 16;
            } else if (c < 2 * CA) {
                int cc = c - CA, r = cc >> 2, p = cc & 3;
                src = Al_g + (size_t)(m0 + r) * K + k0 + p * 8;
                dst = st + SA + r * 80 + p * 16;
            } else if (c < 2 * CA + CB) {
                int cc = c - 2 * CA, r = cc >> 2, p = cc & 3;
                src = Bh_g + (size_t)(n0 + r) * K + k0 + p * 8;
                dst = st + 2 * SA + r * 80 + p * 16;
            } else {
                int cc = c - 2 * CA - CB, r = cc >> 2, p = cc & 3;
                src = Bl_g + (size_t)(n0 + r) * K + k0 + p * 8;
                dst = st + 2 * SA + SB + r * 80 + p * 16;
            }
            cpa16(dst, src);
        }
    };

    float acc[MFRAG][NFRAG][4] = {};

    issue(0); CP_COMMIT;
    issue(1); CP_COMMIT;

    for (int ch = 0; ch < nch; ch++) {
        if (ch + 2 < nch)      { issue(ch + 2); CP_COMMIT; CP_WAIT(2); }
        else if (ch + 1 < nch) { CP_WAIT(1); }
        else                   { CP_WAIT(0); }
        __syncthreads();

        const uint32_t st = base + (ch % 3) * STAGE;
        const uint32_t Bhs = st + 2 * SA;
        #pragma unroll
        for (int ks = 0; ks < 2; ks++) {
            uint32_t ah[MFRAG][4], al[MFRAG][4], bh[NFRAG][2], bl[NFRAG][2];
            const uint32_t a_off =
                (uint32_t)((lane & 15) * 80 + (lane >> 4) * 16 + ks * 32);
            #pragma unroll
            for (int mf = 0; mf < MFRAG; mf++) {
                uint32_t ad = st + (uint32_t)((wm * WM_ + mf * 16) * 80) + a_off;
                ldm_x4(ah[mf][0], ah[mf][1], ah[mf][2], ah[mf][3], ad);
                ldm_x4(al[mf][0], al[mf][1], al[mf][2], al[mf][3], ad + SA);
            }
            const uint32_t b_off =
                (uint32_t)(((lane & 7) + ((lane >> 4) & 1) * 8) * 80
                           + ((lane >> 3) & 1) * 16 + ks * 32);
            #pragma unroll
            for (int nf2 = 0; nf2 < NFRAG / 2; nf2++) {
                uint32_t bd = Bhs + (uint32_t)((wn * WN_ + nf2 * 16) * 80) + b_off;
                ldm_x4(bh[2 * nf2][0], bh[2 * nf2][1],
                       bh[2 * nf2 + 1][0], bh[2 * nf2 + 1][1], bd);
                ldm_x4(bl[2 * nf2][0], bl[2 * nf2][1],
                       bl[2 * nf2 + 1][0], bl[2 * nf2 + 1][1], bd + SB);
            }
            #pragma unroll
            for (int mf = 0; mf < MFRAG; mf++)
                #pragma unroll
                for (int nf = 0; nf < NFRAG; nf++) {
                    mma_bf16(acc[mf][nf], ah[mf], bh[nf]);
                    mma_bf16(acc[mf][nf], ah[mf], bl[nf]);
                    mma_bf16(acc[mf][nf], al[mf], bh[nf]);
                }
        }
        __syncthreads();
    }

    // Epilogue
    const int g = lane >> 2, tig = lane & 3;
    #pragma unroll
    for (int mf = 0; mf < MFRAG; mf++) {
        const int r0 = m0 + wm * WM_ + mf * 16 + g;
        #pragma unroll
        for (int nf = 0; nf < NFRAG; nf++) {
            const int cN = n0 + wn * WN_ + nf * 8 + tig * 2;
            const float b0v = bias[cN], b1v = bias[cN + 1];
            float v00 = acc[mf][nf][0] + b0v, v01 = acc[mf][nf][1] + b1v;
            float v10 = acc[mf][nf][2] + b0v, v11 = acc[mf][nf][3] + b1v;
            if (OUT == 0) {
                *(float2*)&C[(size_t)r0 * NC + cN] = make_float2(v00, v01);
                *(float2*)&C[(size_t)(r0 + 8) * NC + cN] = make_float2(v10, v11);
            } else {
                uint32_t h0, l0, h1, l1;
                if (cN < 1024) {   // Q: scale 1/8
                    split2(v00 * 0.125f, v01 * 0.125f, h0, l0);
                    split2(v10 * 0.125f, v11 * 0.125f, h1, l1);
                    *(uint32_t*)&Qh[(size_t)r0 * EMB + cN] = h0;
                    *(uint32_t*)&Ql[(size_t)r0 * EMB + cN] = l0;
                    *(uint32_t*)&Qh[(size_t)(r0 + 8) * EMB + cN] = h1;
                    *(uint32_t*)&Ql[(size_t)(r0 + 8) * EMB + cN] = l1;
                } else {           // KV
                    split2(v00, v01, h0, l0);
                    split2(v10, v11, h1, l1);
                    const int ck = cN - 1024;
                    *(uint32_t*)&KVh[(size_t)r0 * 128 + ck] = h0;
                    *(uint32_t*)&KVl[(size_t)r0 * 128 + ck] = l0;
                    *(uint32_t*)&KVh[(size_t)(r0 + 8) * 128 + ck] = h1;
                    *(uint32_t*)&KVl[(size_t)(r0 + 8) * 128 + ck] = l1;
                }
            }
        }
    }
}

// ---------------------------------------------------------------------------
// Split-KV flash attention: grid (16 qblocks, 16 heads, 2 splits).
//   CTA (qb,h,s) handles key tiles [s*(qb+1), (s+1)*(qb+1)) of 64 keys each,
//   writing unnormalized partial (O, m, l). Merge kernel combines.
// ---------------------------------------------------------------------------
#define AROW 144
#define KVST (4 * 64 * AROW)   // 36864 bytes per stage

__global__ void __launch_bounds__(256, 1)
attn_fa_split(const __nv_bfloat16* __restrict__ qh, const __nv_bfloat16* __restrict__ ql,
              const __nv_bfloat16* __restrict__ kvh, const __nv_bfloat16* __restrict__ kvl,
              float* __restrict__ pO, float* __restrict__ pm, float* __restrict__ pl) {
    extern __shared__ char smbuf[];            // 2 * KVST
    const uint32_t sb = smem_u32(smbuf);

    const int tid  = threadIdx.x;
    const int w    = tid >> 5;
    const int lane = tid & 31;
    const int qb   = (int)gridDim.x - 1 - (int)blockIdx.x;  // heavy blocks first
    const int h    = blockIdx.y;
    const int s    = blockIdx.z;
    const int Rg   = qb * 128 + w * 16;

    // ---- Stage Q (pre-scaled, pre-split) ----
    {
        const uint32_t Qlo = sb + 128 * AROW;
        #pragma unroll
        for (int i = 0; i < 8; i++) {
            int c = tid + 256 * i;
            int half = c >> 10;
            int cc = c & 1023;
            int row = cc >> 3, p = cc & 7;
            const __nv_bfloat16* src = (half ? ql : qh)
                + (size_t)(qb * 128 + row) * EMB + h * HD + p * 8;
            uint32_t dst = (half ? Qlo : sb) + row * AROW + p * 16;
            cpa16(dst, src);
        }
        CP_COMMIT; CP_WAIT(0);
        __syncthreads();
    }

    // ---- Persistent Q fragments ----
    uint32_t qfh[4][4], qfl[4][4];
    {
        const uint32_t qa = (uint32_t)((w * 16 + (lane & 15)) * AROW + (lane >> 4) * 16);
        #pragma unroll
        for (int ks = 0; ks < 4; ks++) {
            ldm_x4(qfh[ks][0], qfh[ks][1], qfh[ks][2], qfh[ks][3], sb + qa + ks * 32);
            ldm_x4(qfl[ks][0], qfl[ks][1], qfl[ks][2], qfl[ks][3],
                   sb + 128 * AROW + qa + ks * 32);
        }
    }
    __syncthreads();

    auto issueKV = [&](int t) {
        const uint32_t st = sb + (t & 1) * KVST;
        const int k0 = t * 64;
        #pragma unroll
        for (int i = 0; i < 8; i++) {
            int c = tid + 256 * i;
            int row = c >> 5, q = c & 31;
            int sec = q >> 3, p = q & 7;        // 0:Kh 1:Kl 2:Vh 3:Vl
            const __nv_bfloat16* src = ((sec & 1) ? kvl : kvh)
                + (size_t)(k0 + row) * 128 + ((sec >> 1) ? 64 : 0) + p * 8;
            uint32_t dst = st + sec * (64 * AROW) + row * AROW + p * 16;
            cpa16(dst, src);
        }
    };

    float m0 = -1e30f, m1 = -1e30f, l0 = 0.f, l1 = 0.f;
    float O[8][4] = {};
    const int t0 = s * (qb + 1);
    const int t1 = (s + 1) * (qb + 1);

    issueKV(t0); CP_COMMIT;
    for (int t = t0; t < t1; t++) {
        if (t + 1 < t1) { issueKV(t + 1); CP_COMMIT; CP_WAIT(1); }
        else            { CP_WAIT(0); }
        __syncthreads();

        const uint32_t st = sb + (t & 1) * KVST;
        const uint32_t Kh = st, Kl = st + 64 * AROW;
        const uint32_t Vh = st + 2 * 64 * AROW, Vl = st + 3 * 64 * AROW;
        const int k0 = t * 64;

        if (k0 <= Rg + 15) {
            // ---- S = Q K^T (3-term) ----
            float S[8][4] = {};
            #pragma unroll
            for (int kb = 0; kb < 4; kb++) {
                uint32_t bh[8][2], bl[8][2];
                #pragma unroll
                for (int ng = 0; ng < 4; ng++) {
                    uint32_t boff = (uint32_t)(
                        (ng * 16 + (lane & 7) + ((lane >> 4) & 1) * 8) * AROW
                        + ((lane >> 3) & 1) * 16 + kb * 32);
                    ldm_x4(bh[2 * ng][0], bh[2 * ng][1],
                           bh[2 * ng + 1][0], bh[2 * ng + 1][1], Kh + boff);
                    ldm_x4(bl[2 * ng][0], bl[2 * ng][1],
                           bl[2 * ng + 1][0], bl[2 * ng + 1][1], Kl + boff);
                }
                #pragma unroll
                for (int nf = 0; nf < 8; nf++) {
                    mma_bf16(S[nf], qfh[kb], bh[nf]);
                    mma_bf16(S[nf], qfh[kb], bl[nf]);
                    mma_bf16(S[nf], qfl[kb], bh[nf]);
                }
            }

            const int r0_ = Rg + (lane >> 2);
            const int r1_ = r0_ + 8;

            // ---- Causal mask (diagonal tiles only) ----
            if (k0 + 63 > Rg) {
                #pragma unroll
                for (int nf = 0; nf < 8; nf++) {
                    int key = k0 + nf * 8 + (lane & 3) * 2;
                    if (key     > r0_) S[nf][0] = -1e30f;
                    if (key + 1 > r0_) S[nf][1] = -1e30f;
                    if (key     > r1_) S[nf][2] = -1e30f;
                    if (key + 1 > r1_) S[nf][3] = -1e30f;
                }
            }

            // ---- Online softmax ----
            float mx0 = -1e30f, mx1 = -1e30f;
            #pragma unroll
            for (int nf = 0; nf < 8; nf++) {
                mx0 = fmaxf(mx0, fmaxf(S[nf][0], S[nf][1]));
                mx1 = fmaxf(mx1, fmaxf(S[nf][2], S[nf][3]));
            }
            mx0 = fmaxf(mx0, __shfl_xor_sync(0xFFFFFFFFu, mx0, 1));
            mx0 = fmaxf(mx0, __shfl_xor_sync(0xFFFFFFFFu, mx0, 2));
            mx1 = fmaxf(mx1, __shfl_xor_sync(0xFFFFFFFFu, mx1, 1));
            mx1 = fmaxf(mx1, __shfl_xor_sync(0xFFFFFFFFu, mx1, 2));

            const float nm0 = fmaxf(m0, mx0);
            const float nm1 = fmaxf(m1, mx1);
            const float c0 = __expf(m0 - nm0);
            const float c1 = __expf(m1 - nm1);
            m0 = nm0; m1 = nm1;

            float ps0 = 0.f, ps1 = 0.f;
            #pragma unroll
            for (int nf = 0; nf < 8; nf++) {
                S[nf][0] = __expf(S[nf][0] - nm0);
                S[nf][1] = __expf(S[nf][1] - nm0);
                S[nf][2] = __expf(S[nf][2] - nm1);
                S[nf][3] = __expf(S[nf][3] - nm1);
                ps0 += S[nf][0] + S[nf][1];
                ps1 += S[nf][2] + S[nf][3];
            }
            ps0 += __shfl_xor_sync(0xFFFFFFFFu, ps0, 1);
            ps0 += __shfl_xor_sync(0xFFFFFFFFu, ps0, 2);
            ps1 += __shfl_xor_sync(0xFFFFFFFFu, ps1, 1);
            ps1 += __shfl_xor_sync(0xFFFFFFFFu, ps1, 2);
            l0 = l0 * c0 + ps0;
            l1 = l1 * c1 + ps1;
            #pragma unroll
            for (int nf = 0; nf < 8; nf++) {
                O[nf][0] *= c0; O[nf][1] *= c0;
                O[nf][2] *= c1; O[nf][3] *= c1;
            }

            // ---- O += P V (3-term; P split from S regs) ----
            #pragma unroll
            for (int kb = 0; kb < 4; kb++) {
                uint32_t ah[4], al[4];
                split2(S[2 * kb][0],     S[2 * kb][1],     ah[0], al[0]);
                split2(S[2 * kb][2],     S[2 * kb][3],     ah[1], al[1]);
                split2(S[2 * kb + 1][0], S[2 * kb + 1][1], ah[2], al[2]);
                split2(S[2 * kb + 1][2], S[2 * kb + 1][3], ah[3], al[3]);

                uint32_t vh[8][2], vl[8][2];
                #pragma unroll
                for (int ng = 0; ng < 4; ng++) {
                    uint32_t voff = (uint32_t)(
                        (kb * 16 + (lane & 15)) * AROW
                        + (ng * 16 + (lane >> 4) * 8) * 2);
                    ldm_x4_t(vh[2 * ng][0], vh[2 * ng][1],
                             vh[2 * ng + 1][0], vh[2 * ng + 1][1], Vh + voff);
                    ldm_x4_t(vl[2 * ng][0], vl[2 * ng][1],
                             vl[2 * ng + 1][0], vl[2 * ng + 1][1], Vl + voff);
                }
                #pragma unroll
                for (int nd = 0; nd < 8; nd++) {
                    mma_bf16(O[nd], ah, vh[nd]);
                    mma_bf16(O[nd], al, vh[nd]);
                    mma_bf16(O[nd], ah, vl[nd]);
                }
            }
        }
        __syncthreads();
    }

    // ---- Epilogue: store unnormalized partials ----
    const int r0_ = Rg + (lane >> 2);
    const int r1_ = r0_ + 8;
    const size_t b0 = ((size_t)(s * SEQ) + r0_) * NH + h;
    const size_t b1 = ((size_t)(s * SEQ) + r1_) * NH + h;
    #pragma unroll
    for (int nd = 0; nd < 8; nd++) {
        const int col = nd * 8 + (lane & 3) * 2;
        *(float2*)&pO[b0 * HD + col] = make_float2(O[nd][0], O[nd][1]);
        *(float2*)&pO[b1 * HD + col] = make_float2(O[nd][2], O[nd][3]);
    }
    if ((lane & 3) == 0) {
        pm[b0] = m0; pl[b0] = l0;
        pm[b1] = m1; pl[b1] = l1;
    }
}

// ---------------------------------------------------------------------------
// Merge split partials -> normalized, pre-split bf16 attn output
// ---------------------------------------------------------------------------
__global__ void merge_attn(const float* __restrict__ pO, const float* __restrict__ pm,
                           const float* __restrict__ pl,
                           __nv_bfloat16* __restrict__ ah, __nv_bfloat16* __restrict__ al) {
    int gid = blockIdx.x * 256 + threadIdx.x;   // SEQ*NH*32 threads
    int row = gid >> 9;
    int rem = gid & 511;
    int h  = rem >> 5;
    int d2 = rem & 31;
    size_t i0 = (size_t)row * NH + h;
    size_t i1 = ((size_t)SEQ + row) * NH + h;
    float m0 = pm[i0], m1 = pm[i1];
    float l0 = pl[i0], l1 = pl[i1];
    float m = fmaxf(m0, m1);
    float a0 = __expf(m0 - m), a1 = __expf(m1 - m);
    float inv = 1.f / (l0 * a0 + l1 * a1);
    float2 O0 = *(const float2*)&pO[i0 * HD + d2 * 2];
    float2 O1 = *(const float2*)&pO[i1 * HD + d2 * 2];
    float ox = (O0.x * a0 + O1.x * a1) * inv;
    float oy = (O0.y * a0 + O1.y * a1) * inv;
    uint32_t hh, ll;
    split2(ox, oy, hh, ll);
    size_t off = (size_t)row * EMB + h * HD + d2 * 2;
    *(uint32_t*)&ah[off] = hh;
    *(uint32_t*)&al[off] = ll;
}

// ===========================================================================
// Launch
// Inputs: hidden_states, mask, Wq, bq, Wk, bk, Wv, bv, Wo, bo (mask ignored)
// ===========================================================================
extern "C" void kernel_launch(void* const* d_in, const int* in_sizes, int n_in,
                              void* d_out, int out_size) {
    const float* x  = (const float*)d_in[0];
    const float* Wq = (const float*)d_in[2];
    const float* bq = (const float*)d_in[3];
    const float* Wk = (const float*)d_in[4];
    const float* bk = (const float*)d_in[5];
    const float* Wv = (const float*)d_in[6];
    const float* bv = (const float*)d_in[7];
    const float* Wo = (const float*)d_in[8];
    const float* bo = (const float*)d_in[9];
    float* out = (float*)d_out;

    __nv_bfloat16 *xh, *xl, *wallh, *walll, *woh, *wol;
    __nv_bfloat16 *qh, *ql, *kvh, *kvl, *ah, *al;
    float *ball, *pO, *pm, *pl;
    cudaGetSymbolAddress((void**)&xh, g_xh);     cudaGetSymbolAddress((void**)&xl, g_xl);
    cudaGetSymbolAddress((void**)&wallh, g_wallh); cudaGetSymbolAddress((void**)&walll, g_walll);
    cudaGetSymbolAddress((void**)&woh, g_woh);   cudaGetSymbolAddress((void**)&wol, g_wol);
    cudaGetSymbolAddress((void**)&qh, g_qh);     cudaGetSymbolAddress((void**)&ql, g_ql);
    cudaGetSymbolAddress((void**)&kvh, g_kvh);   cudaGetSymbolAddress((void**)&kvl, g_kvl);
    cudaGetSymbolAddress((void**)&ah, g_ah);     cudaGetSymbolAddress((void**)&al, g_al);
    cudaGetSymbolAddress((void**)&ball, g_ball);
    cudaGetSymbolAddress((void**)&pO, g_pO);
    cudaGetSymbolAddress((void**)&pm, g_pm);
    cudaGetSymbolAddress((void**)&pl, g_pl);

    const int SMEM_GEMM = 3 * (2 * 128 + 2 * 128) * 80;  // 122880
    const int SMEM_ATT  = 2 * KVST;                      // 73728
    cudaFuncSetAttribute((const void*)gemm_pre<128, 128, 64, 1>,
                         cudaFuncAttributeMaxDynamicSharedMemorySize, SMEM_GEMM);
    cudaFuncSetAttribute((const void*)gemm_pre<128, 128, 64, 0>,
                         cudaFuncAttributeMaxDynamicSharedMemorySize, SMEM_GEMM);
    cudaFuncSetAttribute((const void*)attn_fa_split,
                         cudaFuncAttributeMaxDynamicSharedMemorySize, SMEM_ATT);

    // 1. Prep: split everything once (+ bias concat)
    prep_all<<<4225, 256>>>((const float4*)x, (const float4*)Wq, (const float4*)Wk,
                            (const float4*)Wv, (const float4*)Wo, bq, bk, bv);

    // 2. Fused Q|K|V projection (144 CTAs ~= one wave)
    gemm_pre<128, 128, 64, 1><<<dim3(9, 16), 256, SMEM_GEMM>>>(
        xh, xl, wallh, walll, ball, nullptr, qh, ql, kvh, kvl, 0, EMB);

    // 3. Split-KV flash attention -> partials
    attn_fa_split<<<dim3(16, NH, 2), 256, SMEM_ATT>>>(qh, ql, kvh, kvl, pO, pm, pl);

    // 4. Merge partials -> pre-split attn
    merge_attn<<<SEQ * NH * 32 / 256, 256>>>(pO, pm, pl, ah, al);

    // 5. Output projection -> fp32 out
    gemm_pre<128, 128, 64, 0><<<dim3(8, 16), 256, SMEM_GEMM>>>(
        ah, al, woh, wol, bo, out, nullptr, nullptr, nullptr, nullptr, EMB, EMB);
}